// round 13
// baseline (speedup 1.0000x reference)
#include <cuda_runtime.h>
#include <math.h>

#define NN   20000
#define EE   320000
#define CC   64
#define NBF  16
#define RCUT 5.0f
#define CSP  (RCUT/(NBF-1))
#define WIDTH (RCUT/NBF)
#define PI_F 3.14159265358979f
#define FULLMASK 0xffffffffu
#define NB2  2048
#define BINSCALE ((float)NB2/RCUT)
#define SCH  256
#define NBK  ((NN + SCH - 1)/SCH)
#define T1B  ((NN + 63)/64)
#define T3B  ((3*NN + 63)/64)
#define G1B  ((NN + 127)/128)
#define G3B  ((3*NN + 127)/128)
#define APW  4                            // atoms per warp (CSR ownership)
#define AB   ((NN + 8*APW - 1)/(8*APW))   // edge-kernel blocks (8 warps each)
// prep_k block ranges
#define TBB  ((4*NB2*CC + 255)/256)
#define HBB  ((NN*16 + 255)/256)
#define FBB  ((NN*3 + 255)/256)
#define GBB  ((EE + 255)/256)

// ---------------- device scratch ------------------------------------------
static __device__ int   g_cnt;
static __device__ int   g_hist[2*NN];
static __device__ int   g_cur[2*NN];
static __device__ int   g_rowsI[NN+1];
static __device__ int   g_rowsJ[NN+1];
static __device__ int   g_part[2*NBK];
static __device__ __align__(16) int2   g_Iij[EE];
static __device__ __align__(16) float4 g_Im[EE];
static __device__ __align__(16) int2   g_Jij[EE];
static __device__ __align__(16) float4 g_Jm[EE];

// value+slope tables: F[s][bin*CC+ch] = (G, dG), Q[s][...] = (G', dG')
static __device__ __align__(16) float2 g_F[4][NB2*CC];
static __device__ __align__(16) float2 g_Q[4][NB2*CC];

static __device__ __align__(16) float g_h0a[NN*CC];
static __device__ __align__(16) float g_h0b[NN*CC];
static __device__ __align__(16) float g_s0[NN*CC];
static __device__ __align__(16) float g_h1b[NN*3*CC];
static __device__ __align__(16) float g_M[NN*CC*4];      // M0 | (M1 ~ gh1 aliased)
static __device__ __align__(16) float g_gM0[NN*CC];
static __device__ __align__(16) float g_gM1[NN*3*CC];
static __device__ __align__(16) float g_gB[NN*CC];

__device__ __forceinline__ float warpRed(float v){
#pragma unroll
    for(int o=16;o>0;o>>=1) v += __shfl_xor_sync(FULLMASK, v, o);
    return v;
}

__device__ __forceinline__ void dot64(const float* xr, const float* sw, int ws,
                                      float acc[4][4], int tc){
#pragma unroll 8
    for(int k=0;k<64;k++){
        float a0 = xr[k], a1 = xr[65+k], a2 = xr[130+k], a3 = xr[195+k];
        float4 w = *(const float4*)&sw[k*ws + tc*4];
        acc[0][0]=fmaf(a0,w.x,acc[0][0]); acc[0][1]=fmaf(a0,w.y,acc[0][1]);
        acc[0][2]=fmaf(a0,w.z,acc[0][2]); acc[0][3]=fmaf(a0,w.w,acc[0][3]);
        acc[1][0]=fmaf(a1,w.x,acc[1][0]); acc[1][1]=fmaf(a1,w.y,acc[1][1]);
        acc[1][2]=fmaf(a1,w.z,acc[1][2]); acc[1][3]=fmaf(a1,w.w,acc[1][3]);
        acc[2][0]=fmaf(a2,w.x,acc[2][0]); acc[2][1]=fmaf(a2,w.y,acc[2][1]);
        acc[2][2]=fmaf(a2,w.z,acc[2][2]); acc[2][3]=fmaf(a2,w.w,acc[2][3]);
        acc[3][0]=fmaf(a3,w.x,acc[3][0]); acc[3][1]=fmaf(a3,w.y,acc[3][1]);
        acc[3][2]=fmaf(a3,w.z,acc[3][2]); acc[3][3]=fmaf(a3,w.w,acc[3][3]);
    }
}

// ---------------- prep: tables + embedding + F zero + histogram ------------
__global__ void prep_k(const float* __restrict__ Wr, const float* __restrict__ br,
                       const float* __restrict__ emb, const int* __restrict__ z,
                       float* __restrict__ F,
                       const float* __restrict__ coord,
                       const int* __restrict__ ei, const int* __restrict__ ej)
{
    int blk = blockIdx.x;
    int tid = threadIdx.x;
    if(blk < TBB){
        int idx = blk*256 + tid;
        const int per = NB2*CC;
        if(idx >= 4*per) return;
        int s = idx / per;
        int rem = idx - s*per;
        int l = (s >= 2) ? 1 : 0;
        int p = (s == 1) ? 1 : ((s == 3) ? 2 : 0);
        int bin = rem >> 6;
        int ch  = rem & 63;
        const float hstep = RCUT/(float)NB2;
        const float* W = Wr + ((l*4 + p)*NBF)*CC + ch;
        float bias = br[(l*4 + p)*CC + ch];
        float d0 = (float)bin * hstep;
        float d1 = d0 + hstep;
        float pre0 = bias, q0 = 0.f, pre1 = bias, q1 = 0.f;
#pragma unroll
        for(int b=0;b<NBF;b++){
            float w = W[b*CC];
            float z0 = (d0 - b*CSP)/WIDTH;
            float r0 = expf(-z0*z0);
            pre0 = fmaf(r0, w, pre0);
            q0   = fmaf(r0*(-2.0f*z0/WIDTH), w, q0);
            float z1 = (d1 - b*CSP)/WIDTH;
            float r1 = expf(-z1*z1);
            pre1 = fmaf(r1, w, pre1);
            q1   = fmaf(r1*(-2.0f*z1/WIDTH), w, q1);
        }
        float fc0  = 0.5f*(cosf(PI_F*d0/RCUT) + 1.0f);
        float dfc0 = -0.5f*(PI_F/RCUT)*sinf(PI_F*d0/RCUT);
        float G0 = fc0*pre0;
        float Q0 = fc0*q0 + dfc0*pre0;
        float G1 = 0.f, Q1 = 0.f;
        if(d1 < RCUT){
            float fc1  = 0.5f*(cosf(PI_F*d1/RCUT) + 1.0f);
            float dfc1 = -0.5f*(PI_F/RCUT)*sinf(PI_F*d1/RCUT);
            G1 = fc1*pre1;
            Q1 = fc1*q1 + dfc1*pre1;
        }
        g_F[s][rem] = make_float2(G0, G1 - G0);
        g_Q[s][rem] = make_float2(Q0, Q1 - Q0);
    } else if(blk < TBB + HBB){
        int idx = (blk - TBB)*256 + tid;
        if(idx >= NN*16) return;
        int n = idx >> 4, q = idx & 15;
        int zn = __ldg(&z[n]);
        ((float4*)g_h0a)[idx] = ((const float4*)emb)[zn*16 + q];
    } else if(blk < TBB + HBB + FBB){
        int idx = (blk - TBB - HBB)*256 + tid;
        if(idx < NN*3) F[idx] = 0.f;
    } else {
        int e = (blk - TBB - HBB - FBB)*256 + tid;
        if(e >= EE) return;
        int i = ei[e], j = ej[e];
        float dx = coord[j*3+0] - coord[i*3+0];
        float dy = coord[j*3+1] - coord[i*3+1];
        float dz = coord[j*3+2] - coord[i*3+2];
        float d2 = dx*dx + dy*dy + dz*dz + 1e-12f;
        if(d2 < RCUT*RCUT){
            atomicAdd(&g_hist[i], 1);
            atomicAdd(&g_hist[NN+j], 1);
        }
    }
}

// ---------------- multi-block scan -----------------------------------------
__device__ __forceinline__ int blockExclScan(int v, int tid, int* ws){
    int lane = tid & 31, w = tid >> 5;
    int inc = v;
#pragma unroll
    for(int o=1;o<32;o<<=1){
        int n = __shfl_up_sync(FULLMASK, inc, o);
        if(lane >= o) inc += n;
    }
    if(lane == 31) ws[w] = inc;
    __syncthreads();
    if(w == 0 && lane < 8){
        int x = ws[lane];
#pragma unroll
        for(int o=1;o<8;o<<=1){
            int n = __shfl_up_sync(0xff, x, o);
            if(lane >= o) x += n;
        }
        ws[lane] = x;
    }
    __syncthreads();
    int off = (w > 0) ? ws[w-1] : 0;
    return off + inc - v;
}

__global__ __launch_bounds__(SCH) void scanA_k()
{
    __shared__ int ws[8];
    int blk = blockIdx.x;
    int half = blk / NBK;
    int b = blk - half*NBK;
    int idx = b*SCH + threadIdx.x;
    int v = (idx < NN) ? g_hist[half*NN + idx] : 0;
    int excl = blockExclScan(v, threadIdx.x, ws);
    if(threadIdx.x == SCH-1) g_part[blk] = excl + v;
}

__global__ __launch_bounds__(256) void scanB_k()
{
    __shared__ int ws[8];
    int t = threadIdx.x;
    int v = (t < 2*NBK) ? g_part[t] : 0;
    int excl = blockExclScan(v, t, ws);
    __shared__ int off1;
    if(t == NBK) off1 = excl;
    __syncthreads();
    if(t < 2*NBK) g_part[t] = (t >= NBK) ? (excl - off1) : excl;
    if(t == 0){
        g_cnt = off1;
        g_rowsI[NN] = off1;
        g_rowsJ[NN] = off1;
    }
}

__global__ __launch_bounds__(SCH) void scanC_k()
{
    __shared__ int ws[8];
    int blk = blockIdx.x;
    int half = blk / NBK;
    int b = blk - half*NBK;
    int idx = b*SCH + threadIdx.x;
    int gi = half*NN + idx;
    int v = (idx < NN) ? g_hist[gi] : 0;
    int excl = blockExclScan(v, threadIdx.x, ws);
    if(idx < NN){
        int start = g_part[blk] + excl;
        g_cur[gi] = start;
        if(half == 0) g_rowsI[idx] = start;
        else          g_rowsJ[idx] = start;
        g_hist[gi] = 0;
    }
}

// ---------------- geometry pass 2 ------------------------------------------
__global__ void geomB_k(const float* __restrict__ coord,
                        const int* __restrict__ ei, const int* __restrict__ ej)
{
    int e = blockIdx.x*blockDim.x + threadIdx.x;
    if(e >= EE) return;
    int i = ei[e], j = ej[e];
    float dx = coord[j*3+0] - coord[i*3+0];
    float dy = coord[j*3+1] - coord[i*3+1];
    float dz = coord[j*3+2] - coord[i*3+2];
    float d2 = dx*dx + dy*dy + dz*dz + 1e-12f;
    if(d2 >= RCUT*RCUT) return;
    float d = sqrtf(d2);
    float inv = 1.0f/d;
    float4 m = make_float4(d, dx*inv, dy*inv, dz*inv);
    int2 ij = make_int2(i, j);
    int posI = atomicAdd(&g_cur[i], 1);
    g_Iij[posI] = ij;  g_Im[posI] = m;
    int posJ = atomicAdd(&g_cur[NN+j], 1);
    g_Jij[posJ] = ij;  g_Jm[posJ] = m;
}

#define LERP2(P, fr, ox, oy) { ox = fmaf(fr, (P).y, (P).x); oy = fmaf(fr, (P).w, (P).z); }

// ---------------- forward layer-0 edge kernel (CSR by i) -------------------
__global__ __launch_bounds__(256) void edge_fwd0_k(const float* __restrict__ h0)
{
    int tid = threadIdx.x;
    int w = blockIdx.x*8 + (tid>>5);
    int a0 = w*APW;
    if(a0 >= NN) return;
    int lane = tid & 31;
    int c = 2*lane;
    int aEnd = min(a0 + APW, NN);
    int eBeg = g_rowsI[a0], eEnd = g_rowsI[aEnd];
    const float4* F0t = (const float4*)g_F[0];
    const float4* F1t = (const float4*)g_F[1];
    float* M0 = g_M;
    float* M1 = g_M + NN*CC;

    if(eBeg < eEnd){
        float2 a0c = make_float2(0.f,0.f);
        float2 a1c[3] = {{0,0},{0,0},{0,0}};
        int2   ijn = g_Iij[eBeg];
        float4 mn  = g_Im[eBeg];
        float2 hn  = *(const float2*)&h0[ijn.y*64+c];
        float  tn  = mn.x*BINSCALE; int bn = (int)tn; float frn = tn - bn;
        float4 P0n = F0t[bn*32+lane];
        float4 P1n = F1t[bn*32+lane];
        int curi = ijn.x;

        for(int e=eBeg;e<eEnd;e++){
            int2 ij = ijn; float4 m = mn; float2 h0j = hn; float fr = frn;
            float4 P0 = P0n, P1 = P1n;
            if(e+1 < eEnd){
                ijn = g_Iij[e+1];
                mn  = g_Im[e+1];
                hn  = *(const float2*)&h0[ijn.y*64+c];
                tn = mn.x*BINSCALE; bn = (int)tn; frn = tn - bn;
                P0n = F0t[bn*32+lane];
                P1n = F1t[bn*32+lane];
            }
            if(ij.x != curi){
                *(float2*)&M0[curi*64+c] = a0c;
#pragma unroll
                for(int x=0;x<3;x++) *(float2*)&M1[(curi*3+x)*64+c] = a1c[x];
                a0c = make_float2(0.f,0.f);
#pragma unroll
                for(int x=0;x<3;x++) a1c[x] = make_float2(0.f,0.f);
                curi = ij.x;
            }
            float rh[3] = {m.y, m.z, m.w};
            float G0x, G0y, G1x, G1y;
            LERP2(P0, fr, G0x, G0y);
            LERP2(P1, fr, G1x, G1y);
            a0c.x = fmaf(G0x, h0j.x, a0c.x);
            a0c.y = fmaf(G0y, h0j.y, a0c.y);
            float g1x = G1x*h0j.x, g1y = G1y*h0j.y;
#pragma unroll
            for(int x=0;x<3;x++){
                a1c[x].x = fmaf(g1x, rh[x], a1c[x].x);
                a1c[x].y = fmaf(g1y, rh[x], a1c[x].y);
            }
        }
        *(float2*)&M0[curi*64+c] = a0c;
#pragma unroll
        for(int x=0;x<3;x++) *(float2*)&M1[(curi*3+x)*64+c] = a1c[x];
    }
    // zero rows for zero-degree atoms
    float2 zz = make_float2(0.f,0.f);
    for(int a=a0;a<aEnd;a++){
        if(g_rowsI[a+1] == g_rowsI[a]){
            *(float2*)&M0[a*64+c] = zz;
#pragma unroll
            for(int x=0;x<3;x++) *(float2*)&M1[(a*3+x)*64+c] = zz;
        }
    }
}

// ---------------- forward layer-1 edge kernel (CSR by i) -------------------
__global__ __launch_bounds__(256) void edge_fwd1_k(
    const float* __restrict__ h0, const float* __restrict__ h1)
{
    int tid = threadIdx.x;
    int w = blockIdx.x*8 + (tid>>5);
    int a0 = w*APW;
    if(a0 >= NN) return;
    int lane = tid & 31;
    int c = 2*lane;
    int aEnd = min(a0 + APW, NN);
    int eBeg = g_rowsI[a0], eEnd = g_rowsI[aEnd];
    const float4* F2t = (const float4*)g_F[2];
    const float4* F3t = (const float4*)g_F[3];
    float* M0 = g_M;

    if(eBeg < eEnd){
        float2 a0c = make_float2(0.f,0.f);
        int2   ijn = g_Iij[eBeg];
        float4 mn  = g_Im[eBeg];
        float2 hn  = *(const float2*)&h0[ijn.y*64+c];
        float2 vn0 = *(const float2*)&h1[(ijn.y*3+0)*64+c];
        float2 vn1 = *(const float2*)&h1[(ijn.y*3+1)*64+c];
        float2 vn2 = *(const float2*)&h1[(ijn.y*3+2)*64+c];
        float  tn  = mn.x*BINSCALE; int bn = (int)tn; float frn = tn - bn;
        float4 P0n = F2t[bn*32+lane];
        float4 P1n = F3t[bn*32+lane];
        int curi = ijn.x;

        for(int e=eBeg;e<eEnd;e++){
            int2 ij = ijn; float4 m = mn; float2 h0j = hn; float fr = frn;
            float2 v0 = vn0, v1 = vn1, v2 = vn2;
            float4 P0 = P0n, P1 = P1n;
            if(e+1 < eEnd){
                ijn = g_Iij[e+1];
                mn  = g_Im[e+1];
                hn  = *(const float2*)&h0[ijn.y*64+c];
                vn0 = *(const float2*)&h1[(ijn.y*3+0)*64+c];
                vn1 = *(const float2*)&h1[(ijn.y*3+1)*64+c];
                vn2 = *(const float2*)&h1[(ijn.y*3+2)*64+c];
                tn = mn.x*BINSCALE; bn = (int)tn; frn = tn - bn;
                P0n = F2t[bn*32+lane];
                P1n = F3t[bn*32+lane];
            }
            if(ij.x != curi){
                *(float2*)&M0[curi*64+c] = a0c;
                a0c = make_float2(0.f,0.f);
                curi = ij.x;
            }
            float rh[3] = {m.y, m.z, m.w};
            float G0x, G0y, G2x, G2y;
            LERP2(P0, fr, G0x, G0y);
            LERP2(P1, fr, G2x, G2y);
            float tx = v0.x*rh[0] + v1.x*rh[1] + v2.x*rh[2];
            float ty = v0.y*rh[0] + v1.y*rh[1] + v2.y*rh[2];
            a0c.x += G0x*h0j.x + G2x*tx;
            a0c.y += G0y*h0j.y + G2y*ty;
        }
        *(float2*)&M0[curi*64+c] = a0c;
    }
    float2 zz = make_float2(0.f,0.f);
    for(int a=a0;a<aEnd;a++)
        if(g_rowsI[a+1] == g_rowsI[a]) *(float2*)&M0[a*64+c] = zz;
}

// ---------------- backward layer-0 (CSR by i; h1==0) -----------------------
__global__ __launch_bounds__(256) void edge_bwd0_k(
    const float* __restrict__ h0,
    const float* __restrict__ gM0, const float* __restrict__ gM1,
    float* __restrict__ F)
{
    int tid = threadIdx.x;
    int w = blockIdx.x*8 + (tid>>5);
    int a0 = w*APW;
    if(a0 >= NN) return;
    int lane = tid & 31;
    int c = 2*lane;
    int aEnd = min(a0 + APW, NN);
    int eBeg = g_rowsI[a0], eEnd = g_rowsI[aEnd];
    if(eBeg >= eEnd) return;
    const float4* F1t = (const float4*)g_F[1];
    const float4* Q0t = (const float4*)g_Q[0];
    const float4* Q1t = (const float4*)g_Q[1];

    int2   ijn = g_Iij[eBeg];
    float4 mn  = g_Im[eBeg];
    float2 hn  = *(const float2*)&h0[ijn.y*64+c];
    float  tn  = mn.x*BINSCALE; int bn = (int)tn; float frn = tn - bn;
    float4 PF1n = F1t[bn*32+lane];
    float4 PQ0n = Q0t[bn*32+lane];
    float4 PQ1n = Q1t[bn*32+lane];
    int curi = ijn.x;
    float2 gm0 = *(const float2*)&gM0[curi*64+c];
    float2 gm1[3];
#pragma unroll
    for(int x=0;x<3;x++) gm1[x] = *(const float2*)&gM1[(curi*3+x)*64+c];
    float fi = 0.f;

    for(int e=eBeg;e<eEnd;e++){
        int2 ij = ijn; float4 m = mn; float2 h0j = hn; float fr = frn;
        float4 PF1 = PF1n, PQ0 = PQ0n, PQ1 = PQ1n;
        if(e+1 < eEnd){
            ijn = g_Iij[e+1];
            mn  = g_Im[e+1];
            hn  = *(const float2*)&h0[ijn.y*64+c];
            tn = mn.x*BINSCALE; bn = (int)tn; frn = tn - bn;
            PF1n = F1t[bn*32+lane];
            PQ0n = Q0t[bn*32+lane];
            PQ1n = Q1t[bn*32+lane];
        }
        if(ij.x != curi){
            if(lane < 3) atomicAdd(&F[curi*3+lane], fi);
            fi = 0.f;
            curi = ij.x;
            gm0 = *(const float2*)&gM0[curi*64+c];
#pragma unroll
            for(int x=0;x<3;x++) gm1[x] = *(const float2*)&gM1[(curi*3+x)*64+c];
        }
        int j = ij.y;
        float d = m.x;
        float rh[3] = {m.y, m.z, m.w};
        float G1x, G1y, Q0x, Q0y, Q1x, Q1y;
        LERP2(PF1, fr, G1x, G1y);
        LERP2(PQ0, fr, Q0x, Q0y);
        LERP2(PQ1, fr, Q1x, Q1y);

        float gmrx = gm1[0].x*rh[0] + gm1[1].x*rh[1] + gm1[2].x*rh[2];
        float gmry = gm1[0].y*rh[0] + gm1[1].y*rh[1] + gm1[2].y*rh[2];
        float gf0x = gm0.x*h0j.x, gf0y = gm0.y*h0j.y;
        float gf1x = gmrx*h0j.x,  gf1y = gmry*h0j.y;
        float sd = gf0x*Q0x + gf0y*Q0y + gf1x*Q1x + gf1y*Q1y;
        float f1x = G1x*h0j.x, f1y = G1y*h0j.y;
        float gr0 = gm1[0].x*f1x + gm1[0].y*f1y;
        float gr1 = gm1[1].x*f1x + gm1[1].y*f1y;
        float gr2 = gm1[2].x*f1x + gm1[2].y*f1y;

        sd  = warpRed(sd);
        gr0 = warpRed(gr0);
        gr1 = warpRed(gr1);
        gr2 = warpRed(gr2);

        float gdr = gr0*rh[0] + gr1*rh[1] + gr2*rh[2];
        float invd = 1.0f/d;
        if(lane < 3){
            float gx = (lane==0) ? gr0 : ((lane==1) ? gr1 : gr2);
            float rx = rh[lane];
            float grij = (gx - gdr*rx)*invd + sd*rx;
            fi += grij;
            atomicAdd(&F[j*3+lane], -grij);
        }
    }
    if(lane < 3) atomicAdd(&F[curi*3+lane], fi);
}

// ---------------- backward layer-1 (CSR by j) ------------------------------
// gh0 updated in place (gh0[j] += edge contribution); gh1 direct store.
__global__ __launch_bounds__(256) void edge_bwd1_k(
    const float* __restrict__ h0, const float* __restrict__ h1,
    const float* __restrict__ gM0,
    float* __restrict__ gh0, float* __restrict__ gh1, float* __restrict__ F)
{
    int tid = threadIdx.x;
    int w = blockIdx.x*8 + (tid>>5);
    int a0 = w*APW;
    if(a0 >= NN) return;
    int lane = tid & 31;
    int c = 2*lane;
    int aEnd = min(a0 + APW, NN);
    int eBeg = g_rowsJ[a0], eEnd = g_rowsJ[aEnd];
    const float4* F2t = (const float4*)g_F[2];
    const float4* F3t = (const float4*)g_F[3];
    const float4* Q2t = (const float4*)g_Q[2];
    const float4* Q3t = (const float4*)g_Q[3];

    if(eBeg < eEnd){
        int2   ijn = g_Jij[eBeg];
        float4 mn  = g_Jm[eBeg];
        float2 gmn = *(const float2*)&gM0[ijn.x*64+c];
        float  tn  = mn.x*BINSCALE; int bn = (int)tn; float frn = tn - bn;
        float4 PF2n = F2t[bn*32+lane];
        float4 PF3n = F3t[bn*32+lane];
        float4 PQ2n = Q2t[bn*32+lane];
        float4 PQ3n = Q3t[bn*32+lane];
        int curj = ijn.y;
        float2 h0j = *(const float2*)&h0[curj*64+c];
        float2 gb  = *(const float2*)&gh0[curj*64+c];
        float2 v[3];
#pragma unroll
        for(int x=0;x<3;x++) v[x] = *(const float2*)&h1[(curj*3+x)*64+c];
        float2 acc0 = make_float2(0,0);
        float2 acc1[3] = {{0,0},{0,0},{0,0}};
        float fj = 0.f;

        for(int e=eBeg;e<eEnd;e++){
            int2 ij = ijn; float4 m = mn; float2 gm0 = gmn; float fr = frn;
            float4 PF2 = PF2n, PF3 = PF3n, PQ2 = PQ2n, PQ3 = PQ3n;
            if(e+1 < eEnd){
                ijn = g_Jij[e+1];
                mn  = g_Jm[e+1];
                gmn = *(const float2*)&gM0[ijn.x*64+c];
                tn = mn.x*BINSCALE; bn = (int)tn; frn = tn - bn;
                PF2n = F2t[bn*32+lane];
                PF3n = F3t[bn*32+lane];
                PQ2n = Q2t[bn*32+lane];
                PQ3n = Q3t[bn*32+lane];
            }
            if(ij.y != curj){
                *(float2*)&gh0[curj*64+c] = make_float2(gb.x + acc0.x, gb.y + acc0.y);
#pragma unroll
                for(int x=0;x<3;x++) *(float2*)&gh1[(curj*3+x)*64+c] = acc1[x];
                if(lane < 3) atomicAdd(&F[curj*3+lane], fj);
                acc0 = make_float2(0,0);
#pragma unroll
                for(int x=0;x<3;x++) acc1[x] = make_float2(0,0);
                fj = 0.f;
                curj = ij.y;
                h0j = *(const float2*)&h0[curj*64+c];
                gb  = *(const float2*)&gh0[curj*64+c];
#pragma unroll
                for(int x=0;x<3;x++) v[x] = *(const float2*)&h1[(curj*3+x)*64+c];
            }
            int i = ij.x;
            float d = m.x;
            float rh[3] = {m.y, m.z, m.w};
            float G0x, G0y, G2x, G2y, Q0x, Q0y, Q2x, Q2y;
            LERP2(PF2, fr, G0x, G0y);
            LERP2(PF3, fr, G2x, G2y);
            LERP2(PQ2, fr, Q0x, Q0y);
            LERP2(PQ3, fr, Q2x, Q2y);

            float tx = v[0].x*rh[0] + v[1].x*rh[1] + v[2].x*rh[2];
            float ty = v[0].y*rh[0] + v[1].y*rh[1] + v[2].y*rh[2];
            float sd = gm0.x*(Q0x*h0j.x + Q2x*tx) + gm0.y*(Q0y*h0j.y + Q2y*ty);
            float f2x = G2x*gm0.x, f2y = G2y*gm0.y;
            float gr0 = f2x*v[0].x + f2y*v[0].y;
            float gr1 = f2x*v[1].x + f2y*v[1].y;
            float gr2 = f2x*v[2].x + f2y*v[2].y;

            acc0.x += gm0.x*G0x;
            acc0.y += gm0.y*G0y;
#pragma unroll
            for(int x=0;x<3;x++){
                acc1[x].x += f2x*rh[x];
                acc1[x].y += f2y*rh[x];
            }

            sd  = warpRed(sd);
            gr0 = warpRed(gr0);
            gr1 = warpRed(gr1);
            gr2 = warpRed(gr2);

            float gdr = gr0*rh[0] + gr1*rh[1] + gr2*rh[2];
            float invd = 1.0f/d;
            if(lane < 3){
                float gx = (lane==0) ? gr0 : ((lane==1) ? gr1 : gr2);
                float rx = rh[lane];
                float grij = (gx - gdr*rx)*invd + sd*rx;
                atomicAdd(&F[i*3+lane], grij);
                fj -= grij;
            }
        }
        *(float2*)&gh0[curj*64+c] = make_float2(gb.x + acc0.x, gb.y + acc0.y);
#pragma unroll
        for(int x=0;x<3;x++) *(float2*)&gh1[(curj*3+x)*64+c] = acc1[x];
        if(lane < 3) atomicAdd(&F[curj*3+lane], fj);
    }
    // zero gh1 rows for atoms with no incoming edges (gh0 stays = gB, correct)
    float2 zz = make_float2(0.f,0.f);
    for(int a=a0;a<aEnd;a++)
        if(g_rowsJ[a+1] == g_rowsJ[a]){
#pragma unroll
            for(int x=0;x<3;x++) *(float2*)&gh1[(a*3+x)*64+c] = zz;
        }
}

// ---------------- combined forward node GEMMs ------------------------------
__global__ __launch_bounds__(256) void mmfwdC_k(
    const float* __restrict__ M0, const float* __restrict__ M1,
    const float* __restrict__ h0a,
    const float* __restrict__ Wmsg0, const float* __restrict__ Wself0,
    const float* __restrict__ Wmsg1, const float* __restrict__ b0,
    float* __restrict__ h0b, float* __restrict__ s0, float* __restrict__ h1b)
{
    __shared__ float sW[64*64];
    __shared__ float sX[128*64];
    int tid = threadIdx.x;
    int blk = blockIdx.x;
    bool second = (blk >= G3B);
    const float* A    = second ? M0 : M1;
    const float* W1   = second ? Wmsg0 : Wmsg1;
    const float* B    = second ? h0a : nullptr;
    const float* W2   = second ? Wself0 : nullptr;
    const float* bias = second ? b0 : nullptr;
    float* out  = second ? h0b : h1b;
    float* sOut = second ? s0 : nullptr;
    int rows = second ? NN : 3*NN;
    int row0 = (second ? (blk - G3B) : blk)*128;

    int tc = tid & 15, tr = tid >> 4;
    float acc[8][4];
    if(bias){
        float4 b = *(const float4*)&bias[4*tc];
#pragma unroll
        for(int i=0;i<8;i++){ acc[i][0]=b.x; acc[i][1]=b.y; acc[i][2]=b.z; acc[i][3]=b.w; }
    } else {
#pragma unroll
        for(int i=0;i<8;i++){ acc[i][0]=acc[i][1]=acc[i][2]=acc[i][3]=0.f; }
    }
    int nph = B ? 2 : 1;
    for(int ph=0; ph<nph; ph++){
        const float* Xp = ph ? B : A;
        const float* Wp = ph ? W2 : W1;
        if(ph) __syncthreads();
        for(int k=tid;k<4096;k+=256) sW[k] = Wp[k];
        for(int k=tid;k<8192;k+=256){
            int r = k>>6, c = k&63;
            int gr = row0 + r;
            sX[k] = (gr < rows) ? Xp[gr*64+c] : 0.f;
        }
        __syncthreads();
        const float* xr = &sX[(tr*8)*64];
#pragma unroll 4
        for(int k=0;k<64;k++){
            float4 w = *(const float4*)&sW[k*64 + tc*4];
            float a[8];
#pragma unroll
            for(int i=0;i<8;i++) a[i] = xr[i*64+k];
#pragma unroll
            for(int i=0;i<8;i++){
                acc[i][0]=fmaf(a[i],w.x,acc[i][0]);
                acc[i][1]=fmaf(a[i],w.y,acc[i][1]);
                acc[i][2]=fmaf(a[i],w.z,acc[i][2]);
                acc[i][3]=fmaf(a[i],w.w,acc[i][3]);
            }
        }
    }
#pragma unroll
    for(int i=0;i<8;i++){
        int r = row0 + tr*8 + i;
        if(r >= rows) continue;
        float4 o;
        float* oo = &o.x;
#pragma unroll
        for(int jj=0;jj<4;jj++){
            float u = acc[i][jj];
            if(sOut){
                float sig = 1.f/(1.f + expf(-u));
                oo[jj] = u*sig;
            } else oo[jj] = u;
        }
        if(sOut){
            *(float4*)&sOut[r*64 + tc*4] = make_float4(acc[i][0],acc[i][1],acc[i][2],acc[i][3]);
        }
        *(float4*)&out[r*64 + tc*4] = o;
    }
}

// ---------------- fused layer-1 forward + readout + backward ---------------
__global__ __launch_bounds__(256) void l1_fused_k(
    const float* __restrict__ M0,    const float* __restrict__ h0b,
    const float* __restrict__ Wmsg,  const float* __restrict__ Wself,
    const float* __restrict__ bias,
    const float* __restrict__ Wro1,  const float* __restrict__ bro1,
    const float* __restrict__ Wro2,
    float* __restrict__ gM0, float* __restrict__ gB, int rows)
{
    __shared__ float sW[64*68];
    __shared__ float sX[64*65];
    int tid = threadIdx.x;
    int row0 = blockIdx.x*64;
    int tc = tid & 15, tr = tid >> 4;

    float acc[4][4], u1[4][4];
    {
        float4 b = *(const float4*)&bias[4*tc];
#pragma unroll
        for(int i=0;i<4;i++){ acc[i][0]=b.x; acc[i][1]=b.y; acc[i][2]=b.z; acc[i][3]=b.w; }
    }
    for(int k=tid;k<4096;k+=256) sW[k] = Wmsg[k];
    for(int k=tid;k<4096;k+=256){
        int r = k>>6, c = k&63;
        int gr = row0 + r;
        sX[r*65+c] = (gr < rows) ? M0[gr*64+c] : 0.f;
    }
    __syncthreads();
    dot64(&sX[(tr*4)*65], sW, 64, acc, tc);
    __syncthreads();
    for(int k=tid;k<4096;k+=256) sW[k] = Wself[k];
    for(int k=tid;k<4096;k+=256){
        int r = k>>6, c = k&63;
        int gr = row0 + r;
        sX[r*65+c] = (gr < rows) ? h0b[gr*64+c] : 0.f;
    }
    __syncthreads();
    dot64(&sX[(tr*4)*65], sW, 64, acc, tc);
#pragma unroll
    for(int i=0;i<4;i++)
#pragma unroll
        for(int jj=0;jj<4;jj++) u1[i][jj] = acc[i][jj];
    __syncthreads();
    for(int k=tid;k<4096;k+=256) sW[k] = Wro1[k];
#pragma unroll
    for(int i=0;i<4;i++)
#pragma unroll
        for(int jj=0;jj<4;jj++){
            float u = u1[i][jj];
            float sig = 1.f/(1.f + expf(-u));
            sX[(tr*4+i)*65 + tc*4 + jj] = u*sig;
        }
    {
        float4 b = *(const float4*)&bro1[4*tc];
#pragma unroll
        for(int i=0;i<4;i++){ acc[i][0]=b.x; acc[i][1]=b.y; acc[i][2]=b.z; acc[i][3]=b.w; }
    }
    __syncthreads();
    dot64(&sX[(tr*4)*65], sW, 64, acc, tc);
    __syncthreads();
    {
        float4 ro2v = *(const float4*)&Wro2[4*tc];
#pragma unroll
        for(int i=0;i<4;i++)
#pragma unroll
            for(int jj=0;jj<4;jj++){
                float u = acc[i][jj];
                float sig = 1.f/(1.f + expf(-u));
                sX[(tr*4+i)*65 + tc*4 + jj] = (&ro2v.x)[jj]*sig*fmaf(u, 1.f-sig, 1.f);
            }
    }
    for(int k=tid;k<4096;k+=256){
        int cout = k>>6, dd = k&63;
        sW[dd*68+cout] = Wro1[k];
    }
    __syncthreads();
#pragma unroll
    for(int i=0;i<4;i++){ acc[i][0]=acc[i][1]=acc[i][2]=acc[i][3]=0.f; }
    dot64(&sX[(tr*4)*65], sW, 68, acc, tc);
    __syncthreads();
#pragma unroll
    for(int i=0;i<4;i++)
#pragma unroll
        for(int jj=0;jj<4;jj++){
            float u = u1[i][jj];
            float sig = 1.f/(1.f + expf(-u));
            sX[(tr*4+i)*65 + tc*4 + jj] = acc[i][jj]*sig*fmaf(u, 1.f-sig, 1.f);
        }
    for(int k=tid;k<4096;k+=256){
        int cout = k>>6, dd = k&63;
        sW[dd*68+cout] = Wmsg[k];
    }
    __syncthreads();
#pragma unroll
    for(int i=0;i<4;i++){ acc[i][0]=acc[i][1]=acc[i][2]=acc[i][3]=0.f; }
    dot64(&sX[(tr*4)*65], sW, 68, acc, tc);
#pragma unroll
    for(int i=0;i<4;i++){
        int r = row0 + tr*4 + i;
        if(r >= rows) continue;
        *(float4*)&gM0[r*64 + tc*4] = make_float4(acc[i][0],acc[i][1],acc[i][2],acc[i][3]);
    }
    __syncthreads();
    for(int k=tid;k<4096;k+=256){
        int cout = k>>6, dd = k&63;
        sW[dd*68+cout] = Wself[k];
    }
    __syncthreads();
#pragma unroll
    for(int i=0;i<4;i++){ acc[i][0]=acc[i][1]=acc[i][2]=acc[i][3]=0.f; }
    dot64(&sX[(tr*4)*65], sW, 68, acc, tc);
#pragma unroll
    for(int i=0;i<4;i++){
        int r = row0 + tr*4 + i;
        if(r >= rows) continue;
        *(float4*)&gB[r*64 + tc*4] = make_float4(acc[i][0],acc[i][1],acc[i][2],acc[i][3]);
    }
}

// ---------------- combined layer-0 backward GEMMs --------------------------
__global__ __launch_bounds__(256) void bwd0mm_k(
    const float* __restrict__ gB, const float* __restrict__ s0,
    const float* __restrict__ Wmsg0, float* __restrict__ gM0,
    const float* __restrict__ gh1, const float* __restrict__ Wmsg1,
    float* __restrict__ gM1)
{
    __shared__ float sWt[64*68];
    __shared__ float sG[64*65];
    int tid = threadIdx.x;
    int blk = blockIdx.x;
    const float *G, *S, *W; float* out; int rows, row0;
    if(blk < T1B){ G = gB;  S = s0;      W = Wmsg0; out = gM0; rows = NN;   row0 = blk*64; }
    else         { G = gh1; S = nullptr; W = Wmsg1; out = gM1; rows = 3*NN; row0 = (blk-T1B)*64; }
    int tc = tid & 15, tr = tid >> 4;
    for(int k=tid;k<4096;k+=256){
        int r = k>>6, c = k&63;
        int gr = row0 + r;
        float v = 0.f;
        if(gr < rows){
            float g = G[gr*64+c];
            if(S){
                float x = S[gr*64+c];
                float sig = 1.f/(1.f + expf(-x));
                v = g*sig*fmaf(x, 1.f-sig, 1.f);
            } else v = g;
        }
        sG[r*65+c] = v;
    }
    for(int k=tid;k<4096;k+=256){
        int cout = k>>6, dd = k&63;
        sWt[dd*68+cout] = W[k];
    }
    __syncthreads();
    float acc[4][4];
#pragma unroll
    for(int i=0;i<4;i++){ acc[i][0]=acc[i][1]=acc[i][2]=acc[i][3]=0.f; }
    dot64(&sG[(tr*4)*65], sWt, 68, acc, tc);
#pragma unroll
    for(int i=0;i<4;i++){
        int r = row0 + tr*4 + i;
        if(r >= rows) continue;
        *(float4*)&out[r*64 + tc*4] = make_float4(acc[i][0],acc[i][1],acc[i][2],acc[i][3]);
    }
}

// ---------------- host orchestration ---------------------------------------
extern "C" void kernel_launch(void* const* d_in, const int* in_sizes, int n_in,
                              void* d_out, int out_size)
{
    const float* coord  = (const float*)d_in[0];
    const float* emb    = (const float*)d_in[1];
    const float* Wr     = (const float*)d_in[2];
    const float* br     = (const float*)d_in[3];
    const float* Wself0 = (const float*)d_in[4];
    const float* Wmsg0  = (const float*)d_in[5];
    const float* b0     = (const float*)d_in[6];
    const float* Wmsg1  = (const float*)d_in[7];
    const float* Wro1   = (const float*)d_in[9];
    const float* bro1   = (const float*)d_in[10];
    const float* Wro2   = (const float*)d_in[11];
    const int*   z      = (const int*)d_in[13];
    const int*   ei     = (const int*)d_in[14];
    const int*   ej     = (const int*)d_in[15];
    float* F = (float*)d_out;
    (void)in_sizes; (void)n_in; (void)out_size;

    float *h0a,*h0b,*s0,*h1b,*Mbuf,*gM0p,*gM1p,*gB;
    cudaGetSymbolAddress((void**)&h0a, g_h0a);
    cudaGetSymbolAddress((void**)&h0b, g_h0b);
    cudaGetSymbolAddress((void**)&s0,  g_s0);
    cudaGetSymbolAddress((void**)&h1b, g_h1b);
    cudaGetSymbolAddress((void**)&Mbuf,g_M);
    cudaGetSymbolAddress((void**)&gM0p,g_gM0);
    cudaGetSymbolAddress((void**)&gM1p,g_gM1);
    cudaGetSymbolAddress((void**)&gB,  g_gB);
    float* M0  = Mbuf;
    float* M1  = Mbuf + NN*CC;     // aliased: gh1 overwrites M1 after it is consumed
    float* gh1 = M1;

    prep_k<<<TBB + HBB + FBB + GBB, 256>>>(Wr, br, emb, z, F, coord, ei, ej);
    scanA_k<<<2*NBK, SCH>>>();
    scanB_k<<<1, 256>>>();
    scanC_k<<<2*NBK, SCH>>>();
    geomB_k<<<(EE+255)/256, 256>>>(coord, ei, ej);

    // ---- layer 0 forward (CSR direct-store; no memset needed)
    edge_fwd0_k<<<AB, 256>>>(h0a);
    mmfwdC_k<<<G3B + G1B, 256>>>(M0, M1, h0a, Wmsg0, Wself0, Wmsg1, b0, h0b, s0, h1b);

    // ---- layer 1 forward (edge CSR) + fused node fwd/readout/backward
    edge_fwd1_k<<<AB, 256>>>(h0b, h1b);
    l1_fused_k<<<T1B, 256>>>(M0, h0b, Wmsg0 + 4096, Wself0 + 4096, b0 + 64,
                             Wro1, bro1, Wro2, gM0p, gB, NN);

    // ---- layer 1 backward (CSR by j; gh0 in-place on gB, gh1 direct store)
    edge_bwd1_k<<<AB, 256>>>(h0b, h1b, gM0p, gB, gh1, F);

    // ---- layer 0 backward (combined GEMMs + CSR edge)
    bwd0mm_k<<<T1B + T3B, 256>>>(gB, s0, Wmsg0, gM0p, gh1, Wmsg1, gM1p);
    edge_bwd0_k<<<AB, 256>>>(h0a, gM0p, gM1p, F);
}

// round 14
// speedup vs baseline: 1.0836x; 1.0836x over previous
#include <cuda_runtime.h>
#include <math.h>

#define NN   20000
#define EE   320000
#define CC   64
#define NBF  16
#define RCUT 5.0f
#define CSP  (RCUT/(NBF-1))
#define WIDTH (RCUT/NBF)
#define PI_F 3.14159265358979f
#define FULLMASK 0xffffffffu
#define EPW  16
#define EPB  (8*EPW)
#define NB2  2048
#define BINSCALE ((float)NB2/RCUT)
#define SCH  256
#define NBK  ((NN + SCH - 1)/SCH)
#define T1B  ((NN + 63)/64)
#define T3B  ((3*NN + 63)/64)
#define G1B  ((NN + 127)/128)
#define G3B  ((3*NN + 127)/128)
// prep_k block ranges
#define TBB  ((4*NB2*CC + 255)/256)
#define HBB  ((NN*16 + 255)/256)
#define MBB  ((NN*64 + 255)/256)
#define FBB  ((NN*3 + 255)/256)
#define GBB  ((EE + 255)/256)

// ---------------- device scratch ------------------------------------------
static __device__ int   g_cnt;
static __device__ int   g_hist[2*NN];
static __device__ int   g_cur[2*NN];
static __device__ int   g_part[2*NBK];
static __device__ __align__(16) int2   g_Iij[EE];
static __device__ __align__(16) float4 g_Im[EE];
static __device__ __align__(16) int2   g_Jij[EE];
static __device__ __align__(16) float4 g_Jm[EE];

// value+slope tables: F[s][bin*CC+ch] = (G, dG), Q[s][...] = (G', dG')
// sets: 0=(l0,p0) 1=(l0,p1) 2=(l1,p0) 3=(l1,p2)
static __device__ __align__(16) float2 g_F[4][NB2*CC];
static __device__ __align__(16) float2 g_Q[4][NB2*CC];

static __device__ __align__(16) float g_h0a[NN*CC];
static __device__ __align__(16) float g_h0b[NN*CC];
static __device__ __align__(16) float g_s0[NN*CC];
static __device__ __align__(16) float g_h1b[NN*3*CC];
static __device__ __align__(16) float g_M[NN*CC*4];      // M0 | (M1 ~ gh1 aliased)
static __device__ __align__(16) float g_gM0[NN*CC];
static __device__ __align__(16) float g_gM1[NN*3*CC];
static __device__ __align__(16) float g_gB[NN*CC];

__device__ __forceinline__ float warpRed(float v){
#pragma unroll
    for(int o=16;o>0;o>>=1) v += __shfl_xor_sync(FULLMASK, v, o);
    return v;
}

__device__ __forceinline__ void red2(float* addr, float a, float b){
    asm volatile("red.global.add.v2.f32 [%0], {%1, %2};"
                 :: "l"(addr), "f"(a), "f"(b) : "memory");
}

__device__ __forceinline__ void dot64(const float* xr, const float* sw, int ws,
                                      float acc[4][4], int tc){
#pragma unroll 8
    for(int k=0;k<64;k++){
        float a0 = xr[k], a1 = xr[65+k], a2 = xr[130+k], a3 = xr[195+k];
        float4 w = *(const float4*)&sw[k*ws + tc*4];
        acc[0][0]=fmaf(a0,w.x,acc[0][0]); acc[0][1]=fmaf(a0,w.y,acc[0][1]);
        acc[0][2]=fmaf(a0,w.z,acc[0][2]); acc[0][3]=fmaf(a0,w.w,acc[0][3]);
        acc[1][0]=fmaf(a1,w.x,acc[1][0]); acc[1][1]=fmaf(a1,w.y,acc[1][1]);
        acc[1][2]=fmaf(a1,w.z,acc[1][2]); acc[1][3]=fmaf(a1,w.w,acc[1][3]);
        acc[2][0]=fmaf(a2,w.x,acc[2][0]); acc[2][1]=fmaf(a2,w.y,acc[2][1]);
        acc[2][2]=fmaf(a2,w.z,acc[2][2]); acc[2][3]=fmaf(a2,w.w,acc[2][3]);
        acc[3][0]=fmaf(a3,w.x,acc[3][0]); acc[3][1]=fmaf(a3,w.y,acc[3][1]);
        acc[3][2]=fmaf(a3,w.z,acc[3][2]); acc[3][3]=fmaf(a3,w.w,acc[3][3]);
    }
}

// ---------------- prep: tables + embedding + M zero + F zero + histogram ---
__global__ void prep_k(const float* __restrict__ Wr, const float* __restrict__ br,
                       const float* __restrict__ emb, const int* __restrict__ z,
                       float* __restrict__ F,
                       const float* __restrict__ coord,
                       const int* __restrict__ ei, const int* __restrict__ ej)
{
    int blk = blockIdx.x;
    int tid = threadIdx.x;
    if(blk < TBB){
        int idx = blk*256 + tid;
        const int per = NB2*CC;
        if(idx >= 4*per) return;
        int s = idx / per;
        int rem = idx - s*per;
        int l = (s >= 2) ? 1 : 0;
        int p = (s == 1) ? 1 : ((s == 3) ? 2 : 0);
        int bin = rem >> 6;
        int ch  = rem & 63;
        const float hstep = RCUT/(float)NB2;
        const float* W = Wr + ((l*4 + p)*NBF)*CC + ch;
        float bias = br[(l*4 + p)*CC + ch];
        float d0 = (float)bin * hstep;
        float d1 = d0 + hstep;
        float pre0 = bias, q0 = 0.f, pre1 = bias, q1 = 0.f;
#pragma unroll
        for(int b=0;b<NBF;b++){
            float w = W[b*CC];
            float z0 = (d0 - b*CSP)/WIDTH;
            float r0 = expf(-z0*z0);
            pre0 = fmaf(r0, w, pre0);
            q0   = fmaf(r0*(-2.0f*z0/WIDTH), w, q0);
            float z1 = (d1 - b*CSP)/WIDTH;
            float r1 = expf(-z1*z1);
            pre1 = fmaf(r1, w, pre1);
            q1   = fmaf(r1*(-2.0f*z1/WIDTH), w, q1);
        }
        float fc0  = 0.5f*(cosf(PI_F*d0/RCUT) + 1.0f);
        float dfc0 = -0.5f*(PI_F/RCUT)*sinf(PI_F*d0/RCUT);
        float G0 = fc0*pre0;
        float Q0 = fc0*q0 + dfc0*pre0;
        float G1 = 0.f, Q1 = 0.f;
        if(d1 < RCUT){
            float fc1  = 0.5f*(cosf(PI_F*d1/RCUT) + 1.0f);
            float dfc1 = -0.5f*(PI_F/RCUT)*sinf(PI_F*d1/RCUT);
            G1 = fc1*pre1;
            Q1 = fc1*q1 + dfc1*pre1;
        }
        g_F[s][rem] = make_float2(G0, G1 - G0);
        g_Q[s][rem] = make_float2(Q0, Q1 - Q0);
    } else if(blk < TBB + HBB){
        int idx = (blk - TBB)*256 + tid;
        if(idx >= NN*16) return;
        int n = idx >> 4, q = idx & 15;
        int zn = __ldg(&z[n]);
        ((float4*)g_h0a)[idx] = ((const float4*)emb)[zn*16 + q];
    } else if(blk < TBB + HBB + MBB){
        int idx = (blk - TBB - HBB)*256 + tid;
        if(idx < NN*64) ((float4*)g_M)[idx] = make_float4(0.f,0.f,0.f,0.f);
    } else if(blk < TBB + HBB + MBB + FBB){
        int idx = (blk - TBB - HBB - MBB)*256 + tid;
        if(idx < NN*3) F[idx] = 0.f;
    } else {
        int e = (blk - TBB - HBB - MBB - FBB)*256 + tid;
        if(e >= EE) return;
        int i = ei[e], j = ej[e];
        float dx = coord[j*3+0] - coord[i*3+0];
        float dy = coord[j*3+1] - coord[i*3+1];
        float dz = coord[j*3+2] - coord[i*3+2];
        float d2 = dx*dx + dy*dy + dz*dz + 1e-12f;
        if(d2 < RCUT*RCUT){
            atomicAdd(&g_hist[i], 1);
            atomicAdd(&g_hist[NN+j], 1);
        }
    }
}

// ---------------- multi-block scan -----------------------------------------
__device__ __forceinline__ int blockExclScan(int v, int tid, int* ws){
    int lane = tid & 31, w = tid >> 5;
    int inc = v;
#pragma unroll
    for(int o=1;o<32;o<<=1){
        int n = __shfl_up_sync(FULLMASK, inc, o);
        if(lane >= o) inc += n;
    }
    if(lane == 31) ws[w] = inc;
    __syncthreads();
    if(w == 0 && lane < 8){
        int x = ws[lane];
#pragma unroll
        for(int o=1;o<8;o<<=1){
            int n = __shfl_up_sync(0xff, x, o);
            if(lane >= o) x += n;
        }
        ws[lane] = x;
    }
    __syncthreads();
    int off = (w > 0) ? ws[w-1] : 0;
    return off + inc - v;
}

__global__ __launch_bounds__(SCH) void scanA_k()
{
    __shared__ int ws[8];
    int blk = blockIdx.x;
    int half = blk / NBK;
    int b = blk - half*NBK;
    int idx = b*SCH + threadIdx.x;
    int v = (idx < NN) ? g_hist[half*NN + idx] : 0;
    int excl = blockExclScan(v, threadIdx.x, ws);
    if(threadIdx.x == SCH-1) g_part[blk] = excl + v;
}

__global__ __launch_bounds__(256) void scanB_k()
{
    __shared__ int ws[8];
    int t = threadIdx.x;
    int v = (t < 2*NBK) ? g_part[t] : 0;
    int excl = blockExclScan(v, t, ws);
    __shared__ int off1;
    if(t == NBK) off1 = excl;
    __syncthreads();
    if(t < 2*NBK) g_part[t] = (t >= NBK) ? (excl - off1) : excl;
    if(t == 0) g_cnt = off1;
}

__global__ __launch_bounds__(SCH) void scanC_k()
{
    __shared__ int ws[8];
    int blk = blockIdx.x;
    int half = blk / NBK;
    int b = blk - half*NBK;
    int idx = b*SCH + threadIdx.x;
    int gi = half*NN + idx;
    int v = (idx < NN) ? g_hist[gi] : 0;
    int excl = blockExclScan(v, threadIdx.x, ws);
    if(idx < NN){
        g_cur[gi] = g_part[blk] + excl;
        g_hist[gi] = 0;
    }
}

// ---------------- geometry pass 2 ------------------------------------------
__global__ void geomB_k(const float* __restrict__ coord,
                        const int* __restrict__ ei, const int* __restrict__ ej)
{
    int e = blockIdx.x*blockDim.x + threadIdx.x;
    if(e >= EE) return;
    int i = ei[e], j = ej[e];
    float dx = coord[j*3+0] - coord[i*3+0];
    float dy = coord[j*3+1] - coord[i*3+1];
    float dz = coord[j*3+2] - coord[i*3+2];
    float d2 = dx*dx + dy*dy + dz*dz + 1e-12f;
    if(d2 >= RCUT*RCUT) return;
    float d = sqrtf(d2);
    float inv = 1.0f/d;
    float4 m = make_float4(d, dx*inv, dy*inv, dz*inv);
    int2 ij = make_int2(i, j);
    int posI = atomicAdd(&g_cur[i], 1);
    g_Iij[posI] = ij;  g_Im[posI] = m;
    int posJ = atomicAdd(&g_cur[NN+j], 1);
    g_Jij[posJ] = ij;  g_Jm[posJ] = m;
}

// lerp from value+slope float4: (v0, s0, v1, s1) for channels (2l, 2l+1)
#define LERP2(P, fr, ox, oy) { ox = fmaf(fr, (P).y, (P).x); oy = fmaf(fr, (P).w, (P).z); }

// ---------------- forward layer-0 edge kernel (i-sorted) -------------------
__global__ __launch_bounds__(256) void edge_fwd0_k(const float* __restrict__ h0)
{
    int tid = threadIdx.x;
    int cnt = g_cnt;
    int e0 = (blockIdx.x*8 + (tid>>5))*EPW;
    if(e0 >= cnt) return;
    int lane = tid & 31;
    int c = 2*lane;
    int eend = min(e0 + EPW, cnt);
    const float4* F0t = (const float4*)g_F[0];
    const float4* F1t = (const float4*)g_F[1];

    float* M0 = g_M;
    float* M1 = g_M + NN*CC;
    float2 a0c = make_float2(0.f,0.f);
    float2 a1c[3] = {{0,0},{0,0},{0,0}};

    int2   ijn = g_Iij[e0];
    float4 mn  = g_Im[e0];
    float2 hn  = *(const float2*)&h0[ijn.y*64+c];
    float  tn  = mn.x*BINSCALE; int bn = (int)tn; float frn = tn - bn;
    float4 P0n = F0t[bn*32+lane];
    float4 P1n = F1t[bn*32+lane];
    int curi = ijn.x;

    for(int e=e0;e<eend;e++){
        int2 ij = ijn; float4 m = mn; float2 h0j = hn; float fr = frn;
        float4 P0 = P0n, P1 = P1n;
        if(e+1 < eend){
            ijn = g_Iij[e+1];
            mn  = g_Im[e+1];
            hn  = *(const float2*)&h0[ijn.y*64+c];
            tn = mn.x*BINSCALE; bn = (int)tn; frn = tn - bn;
            P0n = F0t[bn*32+lane];
            P1n = F1t[bn*32+lane];
        }
        if(ij.x != curi){
            red2(&M0[curi*64+c], a0c.x, a0c.y);
#pragma unroll
            for(int x=0;x<3;x++) red2(&M1[(curi*3+x)*64+c], a1c[x].x, a1c[x].y);
            a0c = make_float2(0.f,0.f);
#pragma unroll
            for(int x=0;x<3;x++) a1c[x] = make_float2(0.f,0.f);
            curi = ij.x;
        }
        float rh[3] = {m.y, m.z, m.w};
        float G0x, G0y, G1x, G1y;
        LERP2(P0, fr, G0x, G0y);
        LERP2(P1, fr, G1x, G1y);
        a0c.x = fmaf(G0x, h0j.x, a0c.x);
        a0c.y = fmaf(G0y, h0j.y, a0c.y);
        float g1x = G1x*h0j.x, g1y = G1y*h0j.y;
#pragma unroll
        for(int x=0;x<3;x++){
            a1c[x].x = fmaf(g1x, rh[x], a1c[x].x);
            a1c[x].y = fmaf(g1y, rh[x], a1c[x].y);
        }
    }
    red2(&M0[curi*64+c], a0c.x, a0c.y);
#pragma unroll
    for(int x=0;x<3;x++) red2(&M1[(curi*3+x)*64+c], a1c[x].x, a1c[x].y);
}

// ---------------- forward layer-1 edge kernel (i-sorted) -------------------
__global__ __launch_bounds__(256) void edge_fwd1_k(
    const float* __restrict__ h0, const float* __restrict__ h1)
{
    int tid = threadIdx.x;
    int cnt = g_cnt;
    int e0 = (blockIdx.x*8 + (tid>>5))*EPW;
    if(e0 >= cnt) return;
    int lane = tid & 31;
    int c = 2*lane;
    int eend = min(e0 + EPW, cnt);
    const float4* F2t = (const float4*)g_F[2];
    const float4* F3t = (const float4*)g_F[3];

    float* M0 = g_M;
    float2 a0c = make_float2(0.f,0.f);

    int2   ijn = g_Iij[e0];
    float4 mn  = g_Im[e0];
    float2 hn  = *(const float2*)&h0[ijn.y*64+c];
    float2 vn0 = *(const float2*)&h1[(ijn.y*3+0)*64+c];
    float2 vn1 = *(const float2*)&h1[(ijn.y*3+1)*64+c];
    float2 vn2 = *(const float2*)&h1[(ijn.y*3+2)*64+c];
    float  tn  = mn.x*BINSCALE; int bn = (int)tn; float frn = tn - bn;
    float4 P0n = F2t[bn*32+lane];
    float4 P1n = F3t[bn*32+lane];
    int curi = ijn.x;

    for(int e=e0;e<eend;e++){
        int2 ij = ijn; float4 m = mn; float2 h0j = hn; float fr = frn;
        float2 v0 = vn0, v1 = vn1, v2 = vn2;
        float4 P0 = P0n, P1 = P1n;
        if(e+1 < eend){
            ijn = g_Iij[e+1];
            mn  = g_Im[e+1];
            hn  = *(const float2*)&h0[ijn.y*64+c];
            vn0 = *(const float2*)&h1[(ijn.y*3+0)*64+c];
            vn1 = *(const float2*)&h1[(ijn.y*3+1)*64+c];
            vn2 = *(const float2*)&h1[(ijn.y*3+2)*64+c];
            tn = mn.x*BINSCALE; bn = (int)tn; frn = tn - bn;
            P0n = F2t[bn*32+lane];
            P1n = F3t[bn*32+lane];
        }
        if(ij.x != curi){
            red2(&M0[curi*64+c], a0c.x, a0c.y);
            a0c = make_float2(0.f,0.f);
            curi = ij.x;
        }
        float rh[3] = {m.y, m.z, m.w};
        float G0x, G0y, G2x, G2y;
        LERP2(P0, fr, G0x, G0y);
        LERP2(P1, fr, G2x, G2y);
        float tx = v0.x*rh[0] + v1.x*rh[1] + v2.x*rh[2];
        float ty = v0.y*rh[0] + v1.y*rh[1] + v2.y*rh[2];
        a0c.x += G0x*h0j.x + G2x*tx;
        a0c.y += G0y*h0j.y + G2y*ty;
    }
    red2(&M0[curi*64+c], a0c.x, a0c.y);
}

// ---------------- backward layer-0 (i-sorted; h1==0) -----------------------
__global__ __launch_bounds__(256) void edge_bwd0_k(
    const float* __restrict__ h0,
    const float* __restrict__ gM0, const float* __restrict__ gM1,
    float* __restrict__ F)
{
    int tid = threadIdx.x;
    int cnt = g_cnt;
    int e0 = (blockIdx.x*8 + (tid>>5))*EPW;
    if(e0 >= cnt) return;
    int lane = tid & 31;
    int c = 2*lane;
    int eend = min(e0 + EPW, cnt);
    const float4* F1t = (const float4*)g_F[1];
    const float4* Q0t = (const float4*)g_Q[0];
    const float4* Q1t = (const float4*)g_Q[1];

    int2   ijn = g_Iij[e0];
    float4 mn  = g_Im[e0];
    float2 hn  = *(const float2*)&h0[ijn.y*64+c];
    float  tn  = mn.x*BINSCALE; int bn = (int)tn; float frn = tn - bn;
    float4 PF1n = F1t[bn*32+lane];
    float4 PQ0n = Q0t[bn*32+lane];
    float4 PQ1n = Q1t[bn*32+lane];
    int curi = ijn.x;
    float2 gm0 = *(const float2*)&gM0[curi*64+c];
    float2 gm1[3];
#pragma unroll
    for(int x=0;x<3;x++) gm1[x] = *(const float2*)&gM1[(curi*3+x)*64+c];
    float fi = 0.f;

    for(int e=e0;e<eend;e++){
        int2 ij = ijn; float4 m = mn; float2 h0j = hn; float fr = frn;
        float4 PF1 = PF1n, PQ0 = PQ0n, PQ1 = PQ1n;
        if(e+1 < eend){
            ijn = g_Iij[e+1];
            mn  = g_Im[e+1];
            hn  = *(const float2*)&h0[ijn.y*64+c];
            tn = mn.x*BINSCALE; bn = (int)tn; frn = tn - bn;
            PF1n = F1t[bn*32+lane];
            PQ0n = Q0t[bn*32+lane];
            PQ1n = Q1t[bn*32+lane];
        }
        if(ij.x != curi){
            if(lane < 3) atomicAdd(&F[curi*3+lane], fi);
            fi = 0.f;
            curi = ij.x;
            gm0 = *(const float2*)&gM0[curi*64+c];
#pragma unroll
            for(int x=0;x<3;x++) gm1[x] = *(const float2*)&gM1[(curi*3+x)*64+c];
        }
        int j = ij.y;
        float d = m.x;
        float rh[3] = {m.y, m.z, m.w};
        float G1x, G1y, Q0x, Q0y, Q1x, Q1y;
        LERP2(PF1, fr, G1x, G1y);
        LERP2(PQ0, fr, Q0x, Q0y);
        LERP2(PQ1, fr, Q1x, Q1y);

        float gmrx = gm1[0].x*rh[0] + gm1[1].x*rh[1] + gm1[2].x*rh[2];
        float gmry = gm1[0].y*rh[0] + gm1[1].y*rh[1] + gm1[2].y*rh[2];
        float gf0x = gm0.x*h0j.x, gf0y = gm0.y*h0j.y;
        float gf1x = gmrx*h0j.x,  gf1y = gmry*h0j.y;
        float sd = gf0x*Q0x + gf0y*Q0y + gf1x*Q1x + gf1y*Q1y;
        float f1x = G1x*h0j.x, f1y = G1y*h0j.y;
        float gr0 = gm1[0].x*f1x + gm1[0].y*f1y;
        float gr1 = gm1[1].x*f1x + gm1[1].y*f1y;
        float gr2 = gm1[2].x*f1x + gm1[2].y*f1y;

        sd  = warpRed(sd);
        gr0 = warpRed(gr0);
        gr1 = warpRed(gr1);
        gr2 = warpRed(gr2);

        float gdr = gr0*rh[0] + gr1*rh[1] + gr2*rh[2];
        float invd = 1.0f/d;
        if(lane < 3){
            float gx = (lane==0) ? gr0 : ((lane==1) ? gr1 : gr2);
            float rx = rh[lane];
            float grij = (gx - gdr*rx)*invd + sd*rx;
            fi += grij;
            atomicAdd(&F[j*3+lane], -grij);
        }
    }
    if(lane < 3) atomicAdd(&F[curi*3+lane], fi);
}

// ---------------- backward layer-1 (j-sorted) ------------------------------
__global__ __launch_bounds__(256) void edge_bwd1_k(
    const float* __restrict__ h0, const float* __restrict__ h1,
    const float* __restrict__ gM0,
    float* __restrict__ gh0, float* __restrict__ gh1, float* __restrict__ F)
{
    int tid = threadIdx.x;
    int cnt = g_cnt;
    int e0 = (blockIdx.x*8 + (tid>>5))*EPW;
    if(e0 >= cnt) return;
    int lane = tid & 31;
    int c = 2*lane;
    int eend = min(e0 + EPW, cnt);
    const float4* F2t = (const float4*)g_F[2];
    const float4* F3t = (const float4*)g_F[3];
    const float4* Q2t = (const float4*)g_Q[2];
    const float4* Q3t = (const float4*)g_Q[3];

    int2   ijn = g_Jij[e0];
    float4 mn  = g_Jm[e0];
    float2 gmn = *(const float2*)&gM0[ijn.x*64+c];
    float  tn  = mn.x*BINSCALE; int bn = (int)tn; float frn = tn - bn;
    float4 PF2n = F2t[bn*32+lane];
    float4 PF3n = F3t[bn*32+lane];
    float4 PQ2n = Q2t[bn*32+lane];
    float4 PQ3n = Q3t[bn*32+lane];
    int curj = ijn.y;
    float2 h0j = *(const float2*)&h0[curj*64+c];
    float2 v[3];
#pragma unroll
    for(int x=0;x<3;x++) v[x] = *(const float2*)&h1[(curj*3+x)*64+c];
    float2 acc0 = make_float2(0,0);
    float2 acc1[3] = {{0,0},{0,0},{0,0}};
    float fj = 0.f;

    for(int e=e0;e<eend;e++){
        int2 ij = ijn; float4 m = mn; float2 gm0 = gmn; float fr = frn;
        float4 PF2 = PF2n, PF3 = PF3n, PQ2 = PQ2n, PQ3 = PQ3n;
        if(e+1 < eend){
            ijn = g_Jij[e+1];
            mn  = g_Jm[e+1];
            gmn = *(const float2*)&gM0[ijn.x*64+c];
            tn = mn.x*BINSCALE; bn = (int)tn; frn = tn - bn;
            PF2n = F2t[bn*32+lane];
            PF3n = F3t[bn*32+lane];
            PQ2n = Q2t[bn*32+lane];
            PQ3n = Q3t[bn*32+lane];
        }
        if(ij.y != curj){
            red2(&gh0[curj*64+c], acc0.x, acc0.y);
#pragma unroll
            for(int x=0;x<3;x++) red2(&gh1[(curj*3+x)*64+c], acc1[x].x, acc1[x].y);
            if(lane < 3) atomicAdd(&F[curj*3+lane], fj);
            acc0 = make_float2(0,0);
#pragma unroll
            for(int x=0;x<3;x++) acc1[x] = make_float2(0,0);
            fj = 0.f;
            curj = ij.y;
            h0j = *(const float2*)&h0[curj*64+c];
#pragma unroll
            for(int x=0;x<3;x++) v[x] = *(const float2*)&h1[(curj*3+x)*64+c];
        }
        int i = ij.x;
        float d = m.x;
        float rh[3] = {m.y, m.z, m.w};
        float G0x, G0y, G2x, G2y, Q0x, Q0y, Q2x, Q2y;
        LERP2(PF2, fr, G0x, G0y);
        LERP2(PF3, fr, G2x, G2y);
        LERP2(PQ2, fr, Q0x, Q0y);
        LERP2(PQ3, fr, Q2x, Q2y);

        float tx = v[0].x*rh[0] + v[1].x*rh[1] + v[2].x*rh[2];
        float ty = v[0].y*rh[0] + v[1].y*rh[1] + v[2].y*rh[2];
        float sd = gm0.x*(Q0x*h0j.x + Q2x*tx) + gm0.y*(Q0y*h0j.y + Q2y*ty);
        float f2x = G2x*gm0.x, f2y = G2y*gm0.y;
        float gr0 = f2x*v[0].x + f2y*v[0].y;
        float gr1 = f2x*v[1].x + f2y*v[1].y;
        float gr2 = f2x*v[2].x + f2y*v[2].y;

        acc0.x += gm0.x*G0x;
        acc0.y += gm0.y*G0y;
#pragma unroll
        for(int x=0;x<3;x++){
            acc1[x].x += f2x*rh[x];
            acc1[x].y += f2y*rh[x];
        }

        sd  = warpRed(sd);
        gr0 = warpRed(gr0);
        gr1 = warpRed(gr1);
        gr2 = warpRed(gr2);

        float gdr = gr0*rh[0] + gr1*rh[1] + gr2*rh[2];
        float invd = 1.0f/d;
        if(lane < 3){
            float gx = (lane==0) ? gr0 : ((lane==1) ? gr1 : gr2);
            float rx = rh[lane];
            float grij = (gx - gdr*rx)*invd + sd*rx;
            atomicAdd(&F[i*3+lane], grij);
            fj -= grij;
        }
    }
    red2(&gh0[curj*64+c], acc0.x, acc0.y);
#pragma unroll
    for(int x=0;x<3;x++) red2(&gh1[(curj*3+x)*64+c], acc1[x].x, acc1[x].y);
    if(lane < 3) atomicAdd(&F[curj*3+lane], fj);
}

// ---------------- combined forward node GEMMs ------------------------------
__global__ __launch_bounds__(256) void mmfwdC_k(
    const float* __restrict__ M0, const float* __restrict__ M1,
    const float* __restrict__ h0a,
    const float* __restrict__ Wmsg0, const float* __restrict__ Wself0,
    const float* __restrict__ Wmsg1, const float* __restrict__ b0,
    float* __restrict__ h0b, float* __restrict__ s0, float* __restrict__ h1b)
{
    __shared__ float sW[64*64];
    __shared__ float sX[128*64];
    int tid = threadIdx.x;
    int blk = blockIdx.x;
    bool second = (blk >= G3B);
    const float* A    = second ? M0 : M1;
    const float* W1   = second ? Wmsg0 : Wmsg1;
    const float* B    = second ? h0a : nullptr;
    const float* W2   = second ? Wself0 : nullptr;
    const float* bias = second ? b0 : nullptr;
    float* out  = second ? h0b : h1b;
    float* sOut = second ? s0 : nullptr;
    int rows = second ? NN : 3*NN;
    int row0 = (second ? (blk - G3B) : blk)*128;

    int tc = tid & 15, tr = tid >> 4;
    float acc[8][4];
    if(bias){
        float4 b = *(const float4*)&bias[4*tc];
#pragma unroll
        for(int i=0;i<8;i++){ acc[i][0]=b.x; acc[i][1]=b.y; acc[i][2]=b.z; acc[i][3]=b.w; }
    } else {
#pragma unroll
        for(int i=0;i<8;i++){ acc[i][0]=acc[i][1]=acc[i][2]=acc[i][3]=0.f; }
    }
    int nph = B ? 2 : 1;
    for(int ph=0; ph<nph; ph++){
        const float* Xp = ph ? B : A;
        const float* Wp = ph ? W2 : W1;
        if(ph) __syncthreads();
        for(int k=tid;k<4096;k+=256) sW[k] = Wp[k];
        for(int k=tid;k<8192;k+=256){
            int r = k>>6, c = k&63;
            int gr = row0 + r;
            sX[k] = (gr < rows) ? Xp[gr*64+c] : 0.f;
        }
        __syncthreads();
        const float* xr = &sX[(tr*8)*64];
#pragma unroll 4
        for(int k=0;k<64;k++){
            float4 w = *(const float4*)&sW[k*64 + tc*4];
            float a[8];
#pragma unroll
            for(int i=0;i<8;i++) a[i] = xr[i*64+k];
#pragma unroll
            for(int i=0;i<8;i++){
                acc[i][0]=fmaf(a[i],w.x,acc[i][0]);
                acc[i][1]=fmaf(a[i],w.y,acc[i][1]);
                acc[i][2]=fmaf(a[i],w.z,acc[i][2]);
                acc[i][3]=fmaf(a[i],w.w,acc[i][3]);
            }
        }
    }
#pragma unroll
    for(int i=0;i<8;i++){
        int r = row0 + tr*8 + i;
        if(r >= rows) continue;
        float4 o;
        float* oo = &o.x;
#pragma unroll
        for(int jj=0;jj<4;jj++){
            float u = acc[i][jj];
            if(sOut){
                float sig = 1.f/(1.f + expf(-u));
                oo[jj] = u*sig;
            } else oo[jj] = u;
        }
        if(sOut){
            *(float4*)&sOut[r*64 + tc*4] = make_float4(acc[i][0],acc[i][1],acc[i][2],acc[i][3]);
        }
        *(float4*)&out[r*64 + tc*4] = o;
    }
}

// ---------------- fused layer-1 forward + readout + backward ---------------
__global__ __launch_bounds__(256) void l1_fused_k(
    const float* __restrict__ M0,    const float* __restrict__ h0b,
    const float* __restrict__ Wmsg,  const float* __restrict__ Wself,
    const float* __restrict__ bias,
    const float* __restrict__ Wro1,  const float* __restrict__ bro1,
    const float* __restrict__ Wro2,
    float* __restrict__ gM0, float* __restrict__ gB, int rows)
{
    __shared__ float sW[64*68];
    __shared__ float sX[64*65];
    int tid = threadIdx.x;
    int row0 = blockIdx.x*64;
    int tc = tid & 15, tr = tid >> 4;

    float acc[4][4], u1[4][4];
    {
        float4 b = *(const float4*)&bias[4*tc];
#pragma unroll
        for(int i=0;i<4;i++){ acc[i][0]=b.x; acc[i][1]=b.y; acc[i][2]=b.z; acc[i][3]=b.w; }
    }
    for(int k=tid;k<4096;k+=256) sW[k] = Wmsg[k];
    for(int k=tid;k<4096;k+=256){
        int r = k>>6, c = k&63;
        int gr = row0 + r;
        sX[r*65+c] = (gr < rows) ? M0[gr*64+c] : 0.f;
    }
    __syncthreads();
    dot64(&sX[(tr*4)*65], sW, 64, acc, tc);
    __syncthreads();
    for(int k=tid;k<4096;k+=256) sW[k] = Wself[k];
    for(int k=tid;k<4096;k+=256){
        int r = k>>6, c = k&63;
        int gr = row0 + r;
        sX[r*65+c] = (gr < rows) ? h0b[gr*64+c] : 0.f;
    }
    __syncthreads();
    dot64(&sX[(tr*4)*65], sW, 64, acc, tc);
#pragma unroll
    for(int i=0;i<4;i++)
#pragma unroll
        for(int jj=0;jj<4;jj++) u1[i][jj] = acc[i][jj];
    __syncthreads();
    for(int k=tid;k<4096;k+=256) sW[k] = Wro1[k];
#pragma unroll
    for(int i=0;i<4;i++)
#pragma unroll
        for(int jj=0;jj<4;jj++){
            float u = u1[i][jj];
            float sig = 1.f/(1.f + expf(-u));
            sX[(tr*4+i)*65 + tc*4 + jj] = u*sig;
        }
    {
        float4 b = *(const float4*)&bro1[4*tc];
#pragma unroll
        for(int i=0;i<4;i++){ acc[i][0]=b.x; acc[i][1]=b.y; acc[i][2]=b.z; acc[i][3]=b.w; }
    }
    __syncthreads();
    dot64(&sX[(tr*4)*65], sW, 64, acc, tc);
    __syncthreads();
    {
        float4 ro2v = *(const float4*)&Wro2[4*tc];
#pragma unroll
        for(int i=0;i<4;i++)
#pragma unroll
            for(int jj=0;jj<4;jj++){
                float u = acc[i][jj];
                float sig = 1.f/(1.f + expf(-u));
                sX[(tr*4+i)*65 + tc*4 + jj] = (&ro2v.x)[jj]*sig*fmaf(u, 1.f-sig, 1.f);
            }
    }
    for(int k=tid;k<4096;k+=256){
        int cout = k>>6, dd = k&63;
        sW[dd*68+cout] = Wro1[k];
    }
    __syncthreads();
#pragma unroll
    for(int i=0;i<4;i++){ acc[i][0]=acc[i][1]=acc[i][2]=acc[i][3]=0.f; }
    dot64(&sX[(tr*4)*65], sW, 68, acc, tc);
    __syncthreads();
#pragma unroll
    for(int i=0;i<4;i++)
#pragma unroll
        for(int jj=0;jj<4;jj++){
            float u = u1[i][jj];
            float sig = 1.f/(1.f + expf(-u));
            sX[(tr*4+i)*65 + tc*4 + jj] = acc[i][jj]*sig*fmaf(u, 1.f-sig, 1.f);
        }
    for(int k=tid;k<4096;k+=256){
        int cout = k>>6, dd = k&63;
        sW[dd*68+cout] = Wmsg[k];
    }
    __syncthreads();
#pragma unroll
    for(int i=0;i<4;i++){ acc[i][0]=acc[i][1]=acc[i][2]=acc[i][3]=0.f; }
    dot64(&sX[(tr*4)*65], sW, 68, acc, tc);
#pragma unroll
    for(int i=0;i<4;i++){
        int r = row0 + tr*4 + i;
        if(r >= rows) continue;
        *(float4*)&gM0[r*64 + tc*4] = make_float4(acc[i][0],acc[i][1],acc[i][2],acc[i][3]);
    }
    __syncthreads();
    for(int k=tid;k<4096;k+=256){
        int cout = k>>6, dd = k&63;
        sW[dd*68+cout] = Wself[k];
    }
    __syncthreads();
#pragma unroll
    for(int i=0;i<4;i++){ acc[i][0]=acc[i][1]=acc[i][2]=acc[i][3]=0.f; }
    dot64(&sX[(tr*4)*65], sW, 68, acc, tc);
#pragma unroll
    for(int i=0;i<4;i++){
        int r = row0 + tr*4 + i;
        if(r >= rows) continue;
        *(float4*)&gB[r*64 + tc*4] = make_float4(acc[i][0],acc[i][1],acc[i][2],acc[i][3]);
    }
}

// ---------------- combined layer-0 backward GEMMs --------------------------
__global__ __launch_bounds__(256) void bwd0mm_k(
    const float* __restrict__ gB, const float* __restrict__ s0,
    const float* __restrict__ Wmsg0, float* __restrict__ gM0,
    const float* __restrict__ gh1, const float* __restrict__ Wmsg1,
    float* __restrict__ gM1)
{
    __shared__ float sWt[64*68];
    __shared__ float sG[64*65];
    int tid = threadIdx.x;
    int blk = blockIdx.x;
    const float *G, *S, *W; float* out; int rows, row0;
    if(blk < T1B){ G = gB;  S = s0;      W = Wmsg0; out = gM0; rows = NN;   row0 = blk*64; }
    else         { G = gh1; S = nullptr; W = Wmsg1; out = gM1; rows = 3*NN; row0 = (blk-T1B)*64; }
    int tc = tid & 15, tr = tid >> 4;
    for(int k=tid;k<4096;k+=256){
        int r = k>>6, c = k&63;
        int gr = row0 + r;
        float v = 0.f;
        if(gr < rows){
            float g = G[gr*64+c];
            if(S){
                float x = S[gr*64+c];
                float sig = 1.f/(1.f + expf(-x));
                v = g*sig*fmaf(x, 1.f-sig, 1.f);
            } else v = g;
        }
        sG[r*65+c] = v;
    }
    for(int k=tid;k<4096;k+=256){
        int cout = k>>6, dd = k&63;
        sWt[dd*68+cout] = W[k];
    }
    __syncthreads();
    float acc[4][4];
#pragma unroll
    for(int i=0;i<4;i++){ acc[i][0]=acc[i][1]=acc[i][2]=acc[i][3]=0.f; }
    dot64(&sG[(tr*4)*65], sWt, 68, acc, tc);
#pragma unroll
    for(int i=0;i<4;i++){
        int r = row0 + tr*4 + i;
        if(r >= rows) continue;
        *(float4*)&out[r*64 + tc*4] = make_float4(acc[i][0],acc[i][1],acc[i][2],acc[i][3]);
    }
}

// ---------------- host orchestration ---------------------------------------
extern "C" void kernel_launch(void* const* d_in, const int* in_sizes, int n_in,
                              void* d_out, int out_size)
{
    const float* coord  = (const float*)d_in[0];
    const float* emb    = (const float*)d_in[1];
    const float* Wr     = (const float*)d_in[2];
    const float* br     = (const float*)d_in[3];
    const float* Wself0 = (const float*)d_in[4];
    const float* Wmsg0  = (const float*)d_in[5];
    const float* b0     = (const float*)d_in[6];
    const float* Wmsg1  = (const float*)d_in[7];
    const float* Wro1   = (const float*)d_in[9];
    const float* bro1   = (const float*)d_in[10];
    const float* Wro2   = (const float*)d_in[11];
    const int*   z      = (const int*)d_in[13];
    const int*   ei     = (const int*)d_in[14];
    const int*   ej     = (const int*)d_in[15];
    float* F = (float*)d_out;
    (void)in_sizes; (void)n_in; (void)out_size;

    float *h0a,*h0b,*s0,*h1b,*Mbuf,*gM0p,*gM1p,*gB;
    cudaGetSymbolAddress((void**)&h0a, g_h0a);
    cudaGetSymbolAddress((void**)&h0b, g_h0b);
    cudaGetSymbolAddress((void**)&s0,  g_s0);
    cudaGetSymbolAddress((void**)&h1b, g_h1b);
    cudaGetSymbolAddress((void**)&Mbuf,g_M);
    cudaGetSymbolAddress((void**)&gM0p,g_gM0);
    cudaGetSymbolAddress((void**)&gM1p,g_gM1);
    cudaGetSymbolAddress((void**)&gB,  g_gB);
    float* M0  = Mbuf;
    float* M1  = Mbuf + NN*CC;     // aliased: gh1 lives here after M1 is consumed
    float* gh1 = M1;

    const int EB  = (EE + EPB-1)/EPB;

    prep_k<<<TBB + HBB + MBB + FBB + GBB, 256>>>(Wr, br, emb, z, F, coord, ei, ej);
    scanA_k<<<2*NBK, SCH>>>();
    scanB_k<<<1, 256>>>();
    scanC_k<<<2*NBK, SCH>>>();
    geomB_k<<<(EE+255)/256, 256>>>(coord, ei, ej);

    // ---- layer 0 forward
    edge_fwd0_k<<<EB, 256>>>(h0a);
    mmfwdC_k<<<G3B + G1B, 256>>>(M0, M1, h0a, Wmsg0, Wself0, Wmsg1, b0, h0b, s0, h1b);
    cudaMemsetAsync(Mbuf, 0, NN*CC*4*sizeof(float));   // zeros M0 AND gh1 (aliased M1)

    // ---- layer 1 forward (edge) + fused node fwd/readout/backward
    edge_fwd1_k<<<EB, 256>>>(h0b, h1b);
    l1_fused_k<<<T1B, 256>>>(M0, h0b, Wmsg0 + 4096, Wself0 + 4096, b0 + 64,
                             Wro1, bro1, Wro2, gM0p, gB, NN);

    // ---- layer 1 backward (j-sorted scatter)
    edge_bwd1_k<<<EB, 256>>>(h0b, h1b, gM0p, gB, gh1, F);

    // ---- layer 0 backward (combined GEMMs + i-sorted edge)
    bwd0mm_k<<<T1B + T3B, 256>>>(gB, s0, Wmsg0, gM0p, gh1, Wmsg1, gM1p);
    edge_bwd0_k<<<EB, 256>>>(h0a, gM0p, gM1p, F);
}

// round 15
// speedup vs baseline: 1.0857x; 1.0020x over previous
#include <cuda_runtime.h>
#include <math.h>

#define NN   20000
#define EE   320000
#define CC   64
#define NBF  16
#define RCUT 5.0f
#define CSP  (RCUT/(NBF-1))
#define WIDTH (RCUT/NBF)
#define PI_F 3.14159265358979f
#define FULLMASK 0xffffffffu
#define EPW  32
#define EPB  (8*EPW)
#define NB2  2048
#define BINSCALE ((float)NB2/RCUT)
#define SCH  256
#define NBK  ((NN + SCH - 1)/SCH)
#define T1B  ((NN + 63)/64)
#define T3B  ((3*NN + 63)/64)
#define G1B  ((NN + 127)/128)
#define G3B  ((3*NN + 127)/128)
// prep_k block ranges
#define TBB  ((4*NB2*CC + 255)/256)
#define HBB  ((NN*16 + 255)/256)
#define MBB  ((NN*64 + 255)/256)
#define FBB  ((NN*3 + 255)/256)
#define GBB  ((EE + 255)/256)

// ---------------- device scratch ------------------------------------------
static __device__ int   g_cnt;
static __device__ int   g_hist[2*NN];
static __device__ int   g_cur[2*NN];
static __device__ int   g_part[2*NBK];
static __device__ __align__(16) int2   g_Iij[EE];
static __device__ __align__(16) float4 g_Im[EE];
static __device__ __align__(16) int2   g_Jij[EE];
static __device__ __align__(16) float4 g_Jm[EE];

// value+slope tables: F[s][bin*CC+ch] = (G, dG), Q[s][...] = (G', dG')
// sets: 0=(l0,p0) 1=(l0,p1) 2=(l1,p0) 3=(l1,p2)
static __device__ __align__(16) float2 g_F[4][NB2*CC];
static __device__ __align__(16) float2 g_Q[4][NB2*CC];

static __device__ __align__(16) float g_h0a[NN*CC];
static __device__ __align__(16) float g_h0b[NN*CC];
static __device__ __align__(16) float g_s0[NN*CC];
static __device__ __align__(16) float g_h1b[NN*3*CC];
static __device__ __align__(16) float g_M[NN*CC*4];      // M0 | (M1 ~ gh1 aliased)
static __device__ __align__(16) float g_gM0[NN*CC];
static __device__ __align__(16) float g_gM1[NN*3*CC];
static __device__ __align__(16) float g_gB[NN*CC];

__device__ __forceinline__ float warpRed(float v){
#pragma unroll
    for(int o=16;o>0;o>>=1) v += __shfl_xor_sync(FULLMASK, v, o);
    return v;
}

__device__ __forceinline__ void red2(float* addr, float a, float b){
    asm volatile("red.global.add.v2.f32 [%0], {%1, %2};"
                 :: "l"(addr), "f"(a), "f"(b) : "memory");
}

__device__ __forceinline__ void dot64(const float* xr, const float* sw, int ws,
                                      float acc[4][4], int tc){
#pragma unroll 8
    for(int k=0;k<64;k++){
        float a0 = xr[k], a1 = xr[65+k], a2 = xr[130+k], a3 = xr[195+k];
        float4 w = *(const float4*)&sw[k*ws + tc*4];
        acc[0][0]=fmaf(a0,w.x,acc[0][0]); acc[0][1]=fmaf(a0,w.y,acc[0][1]);
        acc[0][2]=fmaf(a0,w.z,acc[0][2]); acc[0][3]=fmaf(a0,w.w,acc[0][3]);
        acc[1][0]=fmaf(a1,w.x,acc[1][0]); acc[1][1]=fmaf(a1,w.y,acc[1][1]);
        acc[1][2]=fmaf(a1,w.z,acc[1][2]); acc[1][3]=fmaf(a1,w.w,acc[1][3]);
        acc[2][0]=fmaf(a2,w.x,acc[2][0]); acc[2][1]=fmaf(a2,w.y,acc[2][1]);
        acc[2][2]=fmaf(a2,w.z,acc[2][2]); acc[2][3]=fmaf(a2,w.w,acc[2][3]);
        acc[3][0]=fmaf(a3,w.x,acc[3][0]); acc[3][1]=fmaf(a3,w.y,acc[3][1]);
        acc[3][2]=fmaf(a3,w.z,acc[3][2]); acc[3][3]=fmaf(a3,w.w,acc[3][3]);
    }
}

// ---------------- prep: tables + embedding + M zero + F zero + histogram ---
__global__ void prep_k(const float* __restrict__ Wr, const float* __restrict__ br,
                       const float* __restrict__ emb, const int* __restrict__ z,
                       float* __restrict__ F,
                       const float* __restrict__ coord,
                       const int* __restrict__ ei, const int* __restrict__ ej)
{
    int blk = blockIdx.x;
    int tid = threadIdx.x;
    if(blk < TBB){
        int idx = blk*256 + tid;
        const int per = NB2*CC;
        if(idx >= 4*per) return;
        int s = idx / per;
        int rem = idx - s*per;
        int l = (s >= 2) ? 1 : 0;
        int p = (s == 1) ? 1 : ((s == 3) ? 2 : 0);
        int bin = rem >> 6;
        int ch  = rem & 63;
        const float hstep = RCUT/(float)NB2;
        const float* W = Wr + ((l*4 + p)*NBF)*CC + ch;
        float bias = br[(l*4 + p)*CC + ch];
        float d0 = (float)bin * hstep;
        float d1 = d0 + hstep;
        float pre0 = bias, q0 = 0.f, pre1 = bias, q1 = 0.f;
#pragma unroll
        for(int b=0;b<NBF;b++){
            float w = W[b*CC];
            float z0 = (d0 - b*CSP)/WIDTH;
            float r0 = expf(-z0*z0);
            pre0 = fmaf(r0, w, pre0);
            q0   = fmaf(r0*(-2.0f*z0/WIDTH), w, q0);
            float z1 = (d1 - b*CSP)/WIDTH;
            float r1 = expf(-z1*z1);
            pre1 = fmaf(r1, w, pre1);
            q1   = fmaf(r1*(-2.0f*z1/WIDTH), w, q1);
        }
        float fc0  = 0.5f*(cosf(PI_F*d0/RCUT) + 1.0f);
        float dfc0 = -0.5f*(PI_F/RCUT)*sinf(PI_F*d0/RCUT);
        float G0 = fc0*pre0;
        float Q0 = fc0*q0 + dfc0*pre0;
        float G1 = 0.f, Q1 = 0.f;
        if(d1 < RCUT){
            float fc1  = 0.5f*(cosf(PI_F*d1/RCUT) + 1.0f);
            float dfc1 = -0.5f*(PI_F/RCUT)*sinf(PI_F*d1/RCUT);
            G1 = fc1*pre1;
            Q1 = fc1*q1 + dfc1*pre1;
        }
        g_F[s][rem] = make_float2(G0, G1 - G0);
        g_Q[s][rem] = make_float2(Q0, Q1 - Q0);
    } else if(blk < TBB + HBB){
        int idx = (blk - TBB)*256 + tid;
        if(idx >= NN*16) return;
        int n = idx >> 4, q = idx & 15;
        int zn = __ldg(&z[n]);
        ((float4*)g_h0a)[idx] = ((const float4*)emb)[zn*16 + q];
    } else if(blk < TBB + HBB + MBB){
        int idx = (blk - TBB - HBB)*256 + tid;
        if(idx < NN*64) ((float4*)g_M)[idx] = make_float4(0.f,0.f,0.f,0.f);
    } else if(blk < TBB + HBB + MBB + FBB){
        int idx = (blk - TBB - HBB - MBB)*256 + tid;
        if(idx < NN*3) F[idx] = 0.f;
    } else {
        int e = (blk - TBB - HBB - MBB - FBB)*256 + tid;
        if(e >= EE) return;
        int i = ei[e], j = ej[e];
        float dx = coord[j*3+0] - coord[i*3+0];
        float dy = coord[j*3+1] - coord[i*3+1];
        float dz = coord[j*3+2] - coord[i*3+2];
        float d2 = dx*dx + dy*dy + dz*dz + 1e-12f;
        if(d2 < RCUT*RCUT){
            atomicAdd(&g_hist[i], 1);
            atomicAdd(&g_hist[NN+j], 1);
        }
    }
}

// ---------------- multi-block scan -----------------------------------------
__device__ __forceinline__ int blockExclScan(int v, int tid, int* ws){
    int lane = tid & 31, w = tid >> 5;
    int inc = v;
#pragma unroll
    for(int o=1;o<32;o<<=1){
        int n = __shfl_up_sync(FULLMASK, inc, o);
        if(lane >= o) inc += n;
    }
    if(lane == 31) ws[w] = inc;
    __syncthreads();
    if(w == 0 && lane < 8){
        int x = ws[lane];
#pragma unroll
        for(int o=1;o<8;o<<=1){
            int n = __shfl_up_sync(0xff, x, o);
            if(lane >= o) x += n;
        }
        ws[lane] = x;
    }
    __syncthreads();
    int off = (w > 0) ? ws[w-1] : 0;
    return off + inc - v;
}

__global__ __launch_bounds__(SCH) void scanA_k()
{
    __shared__ int ws[8];
    int blk = blockIdx.x;
    int half = blk / NBK;
    int b = blk - half*NBK;
    int idx = b*SCH + threadIdx.x;
    int v = (idx < NN) ? g_hist[half*NN + idx] : 0;
    int excl = blockExclScan(v, threadIdx.x, ws);
    if(threadIdx.x == SCH-1) g_part[blk] = excl + v;
}

// Phase C: redundant partial-scan per block, then per-element offsets; re-zero hist
__global__ __launch_bounds__(SCH) void scanC_k()
{
    __shared__ int ws[8];
    __shared__ int sOff[2*NBK];
    __shared__ int off1s;
    int t = threadIdx.x;
    int pv = (t < 2*NBK) ? g_part[t] : 0;
    int pexcl = blockExclScan(pv, t, ws);
    if(t == NBK) off1s = pexcl;
    __syncthreads();
    if(t < 2*NBK) sOff[t] = (t >= NBK) ? (pexcl - off1s) : pexcl;
    __syncthreads();

    int blk = blockIdx.x;
    int half = blk / NBK;
    int b = blk - half*NBK;
    int idx = b*SCH + t;
    int gi = half*NN + idx;
    int hv = (idx < NN) ? g_hist[gi] : 0;
    int excl = blockExclScan(hv, t, ws);
    if(idx < NN){
        g_cur[gi] = sOff[blk] + excl;
        g_hist[gi] = 0;
    }
    if(blk == 0 && t == 0) g_cnt = off1s;
}

// ---------------- geometry pass 2 ------------------------------------------
__global__ void geomB_k(const float* __restrict__ coord,
                        const int* __restrict__ ei, const int* __restrict__ ej)
{
    int e = blockIdx.x*blockDim.x + threadIdx.x;
    if(e >= EE) return;
    int i = ei[e], j = ej[e];
    float dx = coord[j*3+0] - coord[i*3+0];
    float dy = coord[j*3+1] - coord[i*3+1];
    float dz = coord[j*3+2] - coord[i*3+2];
    float d2 = dx*dx + dy*dy + dz*dz + 1e-12f;
    if(d2 >= RCUT*RCUT) return;
    float d = sqrtf(d2);
    float inv = 1.0f/d;
    float4 m = make_float4(d, dx*inv, dy*inv, dz*inv);
    int2 ij = make_int2(i, j);
    int posI = atomicAdd(&g_cur[i], 1);
    g_Iij[posI] = ij;  g_Im[posI] = m;
    int posJ = atomicAdd(&g_cur[NN+j], 1);
    g_Jij[posJ] = ij;  g_Jm[posJ] = m;
}

// lerp from value+slope float4: (v0, s0, v1, s1) for channels (2l, 2l+1)
#define LERP2(P, fr, ox, oy) { ox = fmaf(fr, (P).y, (P).x); oy = fmaf(fr, (P).w, (P).z); }

// ---------------- forward layer-0 edge kernel (i-sorted) -------------------
__global__ __launch_bounds__(256) void edge_fwd0_k(const float* __restrict__ h0)
{
    int tid = threadIdx.x;
    int cnt = g_cnt;
    int e0 = (blockIdx.x*8 + (tid>>5))*EPW;
    if(e0 >= cnt) return;
    int lane = tid & 31;
    int c = 2*lane;
    int eend = min(e0 + EPW, cnt);
    const float4* F0t = (const float4*)g_F[0];
    const float4* F1t = (const float4*)g_F[1];

    float* M0 = g_M;
    float* M1 = g_M + NN*CC;
    float2 a0c = make_float2(0.f,0.f);
    float2 a1c[3] = {{0,0},{0,0},{0,0}};

    int2   ijn = g_Iij[e0];
    float4 mn  = g_Im[e0];
    float2 hn  = *(const float2*)&h0[ijn.y*64+c];
    float  tn  = mn.x*BINSCALE; int bn = (int)tn; float frn = tn - bn;
    float4 P0n = F0t[bn*32+lane];
    float4 P1n = F1t[bn*32+lane];
    int curi = ijn.x;

    for(int e=e0;e<eend;e++){
        int2 ij = ijn; float4 m = mn; float2 h0j = hn; float fr = frn;
        float4 P0 = P0n, P1 = P1n;
        if(e+1 < eend){
            ijn = g_Iij[e+1];
            mn  = g_Im[e+1];
            hn  = *(const float2*)&h0[ijn.y*64+c];
            tn = mn.x*BINSCALE; bn = (int)tn; frn = tn - bn;
            P0n = F0t[bn*32+lane];
            P1n = F1t[bn*32+lane];
        }
        if(ij.x != curi){
            red2(&M0[curi*64+c], a0c.x, a0c.y);
#pragma unroll
            for(int x=0;x<3;x++) red2(&M1[(curi*3+x)*64+c], a1c[x].x, a1c[x].y);
            a0c = make_float2(0.f,0.f);
#pragma unroll
            for(int x=0;x<3;x++) a1c[x] = make_float2(0.f,0.f);
            curi = ij.x;
        }
        float rh[3] = {m.y, m.z, m.w};
        float G0x, G0y, G1x, G1y;
        LERP2(P0, fr, G0x, G0y);
        LERP2(P1, fr, G1x, G1y);
        a0c.x = fmaf(G0x, h0j.x, a0c.x);
        a0c.y = fmaf(G0y, h0j.y, a0c.y);
        float g1x = G1x*h0j.x, g1y = G1y*h0j.y;
#pragma unroll
        for(int x=0;x<3;x++){
            a1c[x].x = fmaf(g1x, rh[x], a1c[x].x);
            a1c[x].y = fmaf(g1y, rh[x], a1c[x].y);
        }
    }
    red2(&M0[curi*64+c], a0c.x, a0c.y);
#pragma unroll
    for(int x=0;x<3;x++) red2(&M1[(curi*3+x)*64+c], a1c[x].x, a1c[x].y);
}

// ---------------- forward layer-1 edge kernel (i-sorted) -------------------
__global__ __launch_bounds__(256) void edge_fwd1_k(
    const float* __restrict__ h0, const float* __restrict__ h1)
{
    int tid = threadIdx.x;
    int cnt = g_cnt;
    int e0 = (blockIdx.x*8 + (tid>>5))*EPW;
    if(e0 >= cnt) return;
    int lane = tid & 31;
    int c = 2*lane;
    int eend = min(e0 + EPW, cnt);
    const float4* F2t = (const float4*)g_F[2];
    const float4* F3t = (const float4*)g_F[3];

    float* M0 = g_M;
    float2 a0c = make_float2(0.f,0.f);

    int2   ijn = g_Iij[e0];
    float4 mn  = g_Im[e0];
    float2 hn  = *(const float2*)&h0[ijn.y*64+c];
    float2 vn0 = *(const float2*)&h1[(ijn.y*3+0)*64+c];
    float2 vn1 = *(const float2*)&h1[(ijn.y*3+1)*64+c];
    float2 vn2 = *(const float2*)&h1[(ijn.y*3+2)*64+c];
    float  tn  = mn.x*BINSCALE; int bn = (int)tn; float frn = tn - bn;
    float4 P0n = F2t[bn*32+lane];
    float4 P1n = F3t[bn*32+lane];
    int curi = ijn.x;

    for(int e=e0;e<eend;e++){
        int2 ij = ijn; float4 m = mn; float2 h0j = hn; float fr = frn;
        float2 v0 = vn0, v1 = vn1, v2 = vn2;
        float4 P0 = P0n, P1 = P1n;
        if(e+1 < eend){
            ijn = g_Iij[e+1];
            mn  = g_Im[e+1];
            hn  = *(const float2*)&h0[ijn.y*64+c];
            vn0 = *(const float2*)&h1[(ijn.y*3+0)*64+c];
            vn1 = *(const float2*)&h1[(ijn.y*3+1)*64+c];
            vn2 = *(const float2*)&h1[(ijn.y*3+2)*64+c];
            tn = mn.x*BINSCALE; bn = (int)tn; frn = tn - bn;
            P0n = F2t[bn*32+lane];
            P1n = F3t[bn*32+lane];
        }
        if(ij.x != curi){
            red2(&M0[curi*64+c], a0c.x, a0c.y);
            a0c = make_float2(0.f,0.f);
            curi = ij.x;
        }
        float rh[3] = {m.y, m.z, m.w};
        float G0x, G0y, G2x, G2y;
        LERP2(P0, fr, G0x, G0y);
        LERP2(P1, fr, G2x, G2y);
        float tx = v0.x*rh[0] + v1.x*rh[1] + v2.x*rh[2];
        float ty = v0.y*rh[0] + v1.y*rh[1] + v2.y*rh[2];
        a0c.x += G0x*h0j.x + G2x*tx;
        a0c.y += G0y*h0j.y + G2y*ty;
    }
    red2(&M0[curi*64+c], a0c.x, a0c.y);
}

// ---------------- backward layer-0 (i-sorted; h1==0) -----------------------
__global__ __launch_bounds__(256) void edge_bwd0_k(
    const float* __restrict__ h0,
    const float* __restrict__ gM0, const float* __restrict__ gM1,
    float* __restrict__ F)
{
    int tid = threadIdx.x;
    int cnt = g_cnt;
    int e0 = (blockIdx.x*8 + (tid>>5))*EPW;
    if(e0 >= cnt) return;
    int lane = tid & 31;
    int c = 2*lane;
    int eend = min(e0 + EPW, cnt);
    const float4* F1t = (const float4*)g_F[1];
    const float4* Q0t = (const float4*)g_Q[0];
    const float4* Q1t = (const float4*)g_Q[1];

    int2   ijn = g_Iij[e0];
    float4 mn  = g_Im[e0];
    float2 hn  = *(const float2*)&h0[ijn.y*64+c];
    float  tn  = mn.x*BINSCALE; int bn = (int)tn; float frn = tn - bn;
    float4 PF1n = F1t[bn*32+lane];
    float4 PQ0n = Q0t[bn*32+lane];
    float4 PQ1n = Q1t[bn*32+lane];
    int curi = ijn.x;
    float2 gm0 = *(const float2*)&gM0[curi*64+c];
    float2 gm1[3];
#pragma unroll
    for(int x=0;x<3;x++) gm1[x] = *(const float2*)&gM1[(curi*3+x)*64+c];
    float fi = 0.f;

    for(int e=e0;e<eend;e++){
        int2 ij = ijn; float4 m = mn; float2 h0j = hn; float fr = frn;
        float4 PF1 = PF1n, PQ0 = PQ0n, PQ1 = PQ1n;
        if(e+1 < eend){
            ijn = g_Iij[e+1];
            mn  = g_Im[e+1];
            hn  = *(const float2*)&h0[ijn.y*64+c];
            tn = mn.x*BINSCALE; bn = (int)tn; frn = tn - bn;
            PF1n = F1t[bn*32+lane];
            PQ0n = Q0t[bn*32+lane];
            PQ1n = Q1t[bn*32+lane];
        }
        if(ij.x != curi){
            if(lane < 3) atomicAdd(&F[curi*3+lane], fi);
            fi = 0.f;
            curi = ij.x;
            gm0 = *(const float2*)&gM0[curi*64+c];
#pragma unroll
            for(int x=0;x<3;x++) gm1[x] = *(const float2*)&gM1[(curi*3+x)*64+c];
        }
        int j = ij.y;
        float d = m.x;
        float rh[3] = {m.y, m.z, m.w};
        float G1x, G1y, Q0x, Q0y, Q1x, Q1y;
        LERP2(PF1, fr, G1x, G1y);
        LERP2(PQ0, fr, Q0x, Q0y);
        LERP2(PQ1, fr, Q1x, Q1y);

        float gmrx = gm1[0].x*rh[0] + gm1[1].x*rh[1] + gm1[2].x*rh[2];
        float gmry = gm1[0].y*rh[0] + gm1[1].y*rh[1] + gm1[2].y*rh[2];
        float gf0x = gm0.x*h0j.x, gf0y = gm0.y*h0j.y;
        float gf1x = gmrx*h0j.x,  gf1y = gmry*h0j.y;
        float sd = gf0x*Q0x + gf0y*Q0y + gf1x*Q1x + gf1y*Q1y;
        float f1x = G1x*h0j.x, f1y = G1y*h0j.y;
        float gr0 = gm1[0].x*f1x + gm1[0].y*f1y;
        float gr1 = gm1[1].x*f1x + gm1[1].y*f1y;
        float gr2 = gm1[2].x*f1x + gm1[2].y*f1y;

        sd  = warpRed(sd);
        gr0 = warpRed(gr0);
        gr1 = warpRed(gr1);
        gr2 = warpRed(gr2);

        float gdr = gr0*rh[0] + gr1*rh[1] + gr2*rh[2];
        float invd = 1.0f/d;
        if(lane < 3){
            float gx = (lane==0) ? gr0 : ((lane==1) ? gr1 : gr2);
            float rx = rh[lane];
            float grij = (gx - gdr*rx)*invd + sd*rx;
            fi += grij;
            atomicAdd(&F[j*3+lane], -grij);
        }
    }
    if(lane < 3) atomicAdd(&F[curi*3+lane], fi);
}

// ---------------- backward layer-1 (j-sorted) ------------------------------
__global__ __launch_bounds__(256) void edge_bwd1_k(
    const float* __restrict__ h0, const float* __restrict__ h1,
    const float* __restrict__ gM0,
    float* __restrict__ gh0, float* __restrict__ gh1, float* __restrict__ F)
{
    int tid = threadIdx.x;
    int cnt = g_cnt;
    int e0 = (blockIdx.x*8 + (tid>>5))*EPW;
    if(e0 >= cnt) return;
    int lane = tid & 31;
    int c = 2*lane;
    int eend = min(e0 + EPW, cnt);
    const float4* F2t = (const float4*)g_F[2];
    const float4* F3t = (const float4*)g_F[3];
    const float4* Q2t = (const float4*)g_Q[2];
    const float4* Q3t = (const float4*)g_Q[3];

    int2   ijn = g_Jij[e0];
    float4 mn  = g_Jm[e0];
    float2 gmn = *(const float2*)&gM0[ijn.x*64+c];
    float  tn  = mn.x*BINSCALE; int bn = (int)tn; float frn = tn - bn;
    float4 PF2n = F2t[bn*32+lane];
    float4 PF3n = F3t[bn*32+lane];
    float4 PQ2n = Q2t[bn*32+lane];
    float4 PQ3n = Q3t[bn*32+lane];
    int curj = ijn.y;
    float2 h0j = *(const float2*)&h0[curj*64+c];
    float2 v[3];
#pragma unroll
    for(int x=0;x<3;x++) v[x] = *(const float2*)&h1[(curj*3+x)*64+c];
    float2 acc0 = make_float2(0,0);
    float2 acc1[3] = {{0,0},{0,0},{0,0}};
    float fj = 0.f;

    for(int e=e0;e<eend;e++){
        int2 ij = ijn; float4 m = mn; float2 gm0 = gmn; float fr = frn;
        float4 PF2 = PF2n, PF3 = PF3n, PQ2 = PQ2n, PQ3 = PQ3n;
        if(e+1 < eend){
            ijn = g_Jij[e+1];
            mn  = g_Jm[e+1];
            gmn = *(const float2*)&gM0[ijn.x*64+c];
            tn = mn.x*BINSCALE; bn = (int)tn; frn = tn - bn;
            PF2n = F2t[bn*32+lane];
            PF3n = F3t[bn*32+lane];
            PQ2n = Q2t[bn*32+lane];
            PQ3n = Q3t[bn*32+lane];
        }
        if(ij.y != curj){
            red2(&gh0[curj*64+c], acc0.x, acc0.y);
#pragma unroll
            for(int x=0;x<3;x++) red2(&gh1[(curj*3+x)*64+c], acc1[x].x, acc1[x].y);
            if(lane < 3) atomicAdd(&F[curj*3+lane], fj);
            acc0 = make_float2(0,0);
#pragma unroll
            for(int x=0;x<3;x++) acc1[x] = make_float2(0,0);
            fj = 0.f;
            curj = ij.y;
            h0j = *(const float2*)&h0[curj*64+c];
#pragma unroll
            for(int x=0;x<3;x++) v[x] = *(const float2*)&h1[(curj*3+x)*64+c];
        }
        int i = ij.x;
        float d = m.x;
        float rh[3] = {m.y, m.z, m.w};
        float G0x, G0y, G2x, G2y, Q0x, Q0y, Q2x, Q2y;
        LERP2(PF2, fr, G0x, G0y);
        LERP2(PF3, fr, G2x, G2y);
        LERP2(PQ2, fr, Q0x, Q0y);
        LERP2(PQ3, fr, Q2x, Q2y);

        float tx = v[0].x*rh[0] + v[1].x*rh[1] + v[2].x*rh[2];
        float ty = v[0].y*rh[0] + v[1].y*rh[1] + v[2].y*rh[2];
        float sd = gm0.x*(Q0x*h0j.x + Q2x*tx) + gm0.y*(Q0y*h0j.y + Q2y*ty);
        float f2x = G2x*gm0.x, f2y = G2y*gm0.y;
        float gr0 = f2x*v[0].x + f2y*v[0].y;
        float gr1 = f2x*v[1].x + f2y*v[1].y;
        float gr2 = f2x*v[2].x + f2y*v[2].y;

        acc0.x += gm0.x*G0x;
        acc0.y += gm0.y*G0y;
#pragma unroll
        for(int x=0;x<3;x++){
            acc1[x].x += f2x*rh[x];
            acc1[x].y += f2y*rh[x];
        }

        sd  = warpRed(sd);
        gr0 = warpRed(gr0);
        gr1 = warpRed(gr1);
        gr2 = warpRed(gr2);

        float gdr = gr0*rh[0] + gr1*rh[1] + gr2*rh[2];
        float invd = 1.0f/d;
        if(lane < 3){
            float gx = (lane==0) ? gr0 : ((lane==1) ? gr1 : gr2);
            float rx = rh[lane];
            float grij = (gx - gdr*rx)*invd + sd*rx;
            atomicAdd(&F[i*3+lane], grij);
            fj -= grij;
        }
    }
    red2(&gh0[curj*64+c], acc0.x, acc0.y);
#pragma unroll
    for(int x=0;x<3;x++) red2(&gh1[(curj*3+x)*64+c], acc1[x].x, acc1[x].y);
    if(lane < 3) atomicAdd(&F[curj*3+lane], fj);
}

// ---------------- combined forward node GEMMs ------------------------------
__global__ __launch_bounds__(256) void mmfwdC_k(
    const float* __restrict__ M0, const float* __restrict__ M1,
    const float* __restrict__ h0a,
    const float* __restrict__ Wmsg0, const float* __restrict__ Wself0,
    const float* __restrict__ Wmsg1, const float* __restrict__ b0,
    float* __restrict__ h0b, float* __restrict__ s0, float* __restrict__ h1b)
{
    __shared__ float sW[64*64];
    __shared__ float sX[128*64];
    int tid = threadIdx.x;
    int blk = blockIdx.x;
    bool second = (blk >= G3B);
    const float* A    = second ? M0 : M1;
    const float* W1   = second ? Wmsg0 : Wmsg1;
    const float* B    = second ? h0a : nullptr;
    const float* W2   = second ? Wself0 : nullptr;
    const float* bias = second ? b0 : nullptr;
    float* out  = second ? h0b : h1b;
    float* sOut = second ? s0 : nullptr;
    int rows = second ? NN : 3*NN;
    int row0 = (second ? (blk - G3B) : blk)*128;

    int tc = tid & 15, tr = tid >> 4;
    float acc[8][4];
    if(bias){
        float4 b = *(const float4*)&bias[4*tc];
#pragma unroll
        for(int i=0;i<8;i++){ acc[i][0]=b.x; acc[i][1]=b.y; acc[i][2]=b.z; acc[i][3]=b.w; }
    } else {
#pragma unroll
        for(int i=0;i<8;i++){ acc[i][0]=acc[i][1]=acc[i][2]=acc[i][3]=0.f; }
    }
    int nph = B ? 2 : 1;
    for(int ph=0; ph<nph; ph++){
        const float* Xp = ph ? B : A;
        const float* Wp = ph ? W2 : W1;
        if(ph) __syncthreads();
        for(int k=tid;k<4096;k+=256) sW[k] = Wp[k];
        for(int k=tid;k<8192;k+=256){
            int r = k>>6, c = k&63;
            int gr = row0 + r;
            sX[k] = (gr < rows) ? Xp[gr*64+c] : 0.f;
        }
        __syncthreads();
        const float* xr = &sX[(tr*8)*64];
#pragma unroll 4
        for(int k=0;k<64;k++){
            float4 w = *(const float4*)&sW[k*64 + tc*4];
            float a[8];
#pragma unroll
            for(int i=0;i<8;i++) a[i] = xr[i*64+k];
#pragma unroll
            for(int i=0;i<8;i++){
                acc[i][0]=fmaf(a[i],w.x,acc[i][0]);
                acc[i][1]=fmaf(a[i],w.y,acc[i][1]);
                acc[i][2]=fmaf(a[i],w.z,acc[i][2]);
                acc[i][3]=fmaf(a[i],w.w,acc[i][3]);
            }
        }
    }
#pragma unroll
    for(int i=0;i<8;i++){
        int r = row0 + tr*8 + i;
        if(r >= rows) continue;
        float4 o;
        float* oo = &o.x;
#pragma unroll
        for(int jj=0;jj<4;jj++){
            float u = acc[i][jj];
            if(sOut){
                float sig = 1.f/(1.f + expf(-u));
                oo[jj] = u*sig;
            } else oo[jj] = u;
        }
        if(sOut){
            *(float4*)&sOut[r*64 + tc*4] = make_float4(acc[i][0],acc[i][1],acc[i][2],acc[i][3]);
        }
        *(float4*)&out[r*64 + tc*4] = o;
    }
}

// ---------------- fused layer-1 forward + readout + backward ---------------
__global__ __launch_bounds__(256) void l1_fused_k(
    const float* __restrict__ M0,    const float* __restrict__ h0b,
    const float* __restrict__ Wmsg,  const float* __restrict__ Wself,
    const float* __restrict__ bias,
    const float* __restrict__ Wro1,  const float* __restrict__ bro1,
    const float* __restrict__ Wro2,
    float* __restrict__ gM0, float* __restrict__ gB, int rows)
{
    __shared__ float sW[64*68];
    __shared__ float sX[64*65];
    int tid = threadIdx.x;
    int row0 = blockIdx.x*64;
    int tc = tid & 15, tr = tid >> 4;

    float acc[4][4], u1[4][4];
    {
        float4 b = *(const float4*)&bias[4*tc];
#pragma unroll
        for(int i=0;i<4;i++){ acc[i][0]=b.x; acc[i][1]=b.y; acc[i][2]=b.z; acc[i][3]=b.w; }
    }
    for(int k=tid;k<4096;k+=256) sW[k] = Wmsg[k];
    for(int k=tid;k<4096;k+=256){
        int r = k>>6, c = k&63;
        int gr = row0 + r;
        sX[r*65+c] = (gr < rows) ? M0[gr*64+c] : 0.f;
    }
    __syncthreads();
    dot64(&sX[(tr*4)*65], sW, 64, acc, tc);
    __syncthreads();
    for(int k=tid;k<4096;k+=256) sW[k] = Wself[k];
    for(int k=tid;k<4096;k+=256){
        int r = k>>6, c = k&63;
        int gr = row0 + r;
        sX[r*65+c] = (gr < rows) ? h0b[gr*64+c] : 0.f;
    }
    __syncthreads();
    dot64(&sX[(tr*4)*65], sW, 64, acc, tc);
#pragma unroll
    for(int i=0;i<4;i++)
#pragma unroll
        for(int jj=0;jj<4;jj++) u1[i][jj] = acc[i][jj];
    __syncthreads();
    for(int k=tid;k<4096;k+=256) sW[k] = Wro1[k];
#pragma unroll
    for(int i=0;i<4;i++)
#pragma unroll
        for(int jj=0;jj<4;jj++){
            float u = u1[i][jj];
            float sig = 1.f/(1.f + expf(-u));
            sX[(tr*4+i)*65 + tc*4 + jj] = u*sig;
        }
    {
        float4 b = *(const float4*)&bro1[4*tc];
#pragma unroll
        for(int i=0;i<4;i++){ acc[i][0]=b.x; acc[i][1]=b.y; acc[i][2]=b.z; acc[i][3]=b.w; }
    }
    __syncthreads();
    dot64(&sX[(tr*4)*65], sW, 64, acc, tc);
    __syncthreads();
    {
        float4 ro2v = *(const float4*)&Wro2[4*tc];
#pragma unroll
        for(int i=0;i<4;i++)
#pragma unroll
            for(int jj=0;jj<4;jj++){
                float u = acc[i][jj];
                float sig = 1.f/(1.f + expf(-u));
                sX[(tr*4+i)*65 + tc*4 + jj] = (&ro2v.x)[jj]*sig*fmaf(u, 1.f-sig, 1.f);
            }
    }
    for(int k=tid;k<4096;k+=256){
        int cout = k>>6, dd = k&63;
        sW[dd*68+cout] = Wro1[k];
    }
    __syncthreads();
#pragma unroll
    for(int i=0;i<4;i++){ acc[i][0]=acc[i][1]=acc[i][2]=acc[i][3]=0.f; }
    dot64(&sX[(tr*4)*65], sW, 68, acc, tc);
    __syncthreads();
#pragma unroll
    for(int i=0;i<4;i++)
#pragma unroll
        for(int jj=0;jj<4;jj++){
            float u = u1[i][jj];
            float sig = 1.f/(1.f + expf(-u));
            sX[(tr*4+i)*65 + tc*4 + jj] = acc[i][jj]*sig*fmaf(u, 1.f-sig, 1.f);
        }
    for(int k=tid;k<4096;k+=256){
        int cout = k>>6, dd = k&63;
        sW[dd*68+cout] = Wmsg[k];
    }
    __syncthreads();
#pragma unroll
    for(int i=0;i<4;i++){ acc[i][0]=acc[i][1]=acc[i][2]=acc[i][3]=0.f; }
    dot64(&sX[(tr*4)*65], sW, 68, acc, tc);
#pragma unroll
    for(int i=0;i<4;i++){
        int r = row0 + tr*4 + i;
        if(r >= rows) continue;
        *(float4*)&gM0[r*64 + tc*4] = make_float4(acc[i][0],acc[i][1],acc[i][2],acc[i][3]);
    }
    __syncthreads();
    for(int k=tid;k<4096;k+=256){
        int cout = k>>6, dd = k&63;
        sW[dd*68+cout] = Wself[k];
    }
    __syncthreads();
#pragma unroll
    for(int i=0;i<4;i++){ acc[i][0]=acc[i][1]=acc[i][2]=acc[i][3]=0.f; }
    dot64(&sX[(tr*4)*65], sW, 68, acc, tc);
#pragma unroll
    for(int i=0;i<4;i++){
        int r = row0 + tr*4 + i;
        if(r >= rows) continue;
        *(float4*)&gB[r*64 + tc*4] = make_float4(acc[i][0],acc[i][1],acc[i][2],acc[i][3]);
    }
}

// ---------------- combined layer-0 backward GEMMs --------------------------
__global__ __launch_bounds__(256) void bwd0mm_k(
    const float* __restrict__ gB, const float* __restrict__ s0,
    const float* __restrict__ Wmsg0, float* __restrict__ gM0,
    const float* __restrict__ gh1, const float* __restrict__ Wmsg1,
    float* __restrict__ gM1)
{
    __shared__ float sWt[64*68];
    __shared__ float sG[64*65];
    int tid = threadIdx.x;
    int blk = blockIdx.x;
    const float *G, *S, *W; float* out; int rows, row0;
    if(blk < T1B){ G = gB;  S = s0;      W = Wmsg0; out = gM0; rows = NN;   row0 = blk*64; }
    else         { G = gh1; S = nullptr; W = Wmsg1; out = gM1; rows = 3*NN; row0 = (blk-T1B)*64; }
    int tc = tid & 15, tr = tid >> 4;
    for(int k=tid;k<4096;k+=256){
        int r = k>>6, c = k&63;
        int gr = row0 + r;
        float v = 0.f;
        if(gr < rows){
            float g = G[gr*64+c];
            if(S){
                float x = S[gr*64+c];
                float sig = 1.f/(1.f + expf(-x));
                v = g*sig*fmaf(x, 1.f-sig, 1.f);
            } else v = g;
        }
        sG[r*65+c] = v;
    }
    for(int k=tid;k<4096;k+=256){
        int cout = k>>6, dd = k&63;
        sWt[dd*68+cout] = W[k];
    }
    __syncthreads();
    float acc[4][4];
#pragma unroll
    for(int i=0;i<4;i++){ acc[i][0]=acc[i][1]=acc[i][2]=acc[i][3]=0.f; }
    dot64(&sG[(tr*4)*65], sWt, 68, acc, tc);
#pragma unroll
    for(int i=0;i<4;i++){
        int r = row0 + tr*4 + i;
        if(r >= rows) continue;
        *(float4*)&out[r*64 + tc*4] = make_float4(acc[i][0],acc[i][1],acc[i][2],acc[i][3]);
    }
}

// ---------------- host orchestration ---------------------------------------
extern "C" void kernel_launch(void* const* d_in, const int* in_sizes, int n_in,
                              void* d_out, int out_size)
{
    const float* coord  = (const float*)d_in[0];
    const float* emb    = (const float*)d_in[1];
    const float* Wr     = (const float*)d_in[2];
    const float* br     = (const float*)d_in[3];
    const float* Wself0 = (const float*)d_in[4];
    const float* Wmsg0  = (const float*)d_in[5];
    const float* b0     = (const float*)d_in[6];
    const float* Wmsg1  = (const float*)d_in[7];
    const float* Wro1   = (const float*)d_in[9];
    const float* bro1   = (const float*)d_in[10];
    const float* Wro2   = (const float*)d_in[11];
    const int*   z      = (const int*)d_in[13];
    const int*   ei     = (const int*)d_in[14];
    const int*   ej     = (const int*)d_in[15];
    float* F = (float*)d_out;
    (void)in_sizes; (void)n_in; (void)out_size;

    float *h0a,*h0b,*s0,*h1b,*Mbuf,*gM0p,*gM1p,*gB;
    cudaGetSymbolAddress((void**)&h0a, g_h0a);
    cudaGetSymbolAddress((void**)&h0b, g_h0b);
    cudaGetSymbolAddress((void**)&s0,  g_s0);
    cudaGetSymbolAddress((void**)&h1b, g_h1b);
    cudaGetSymbolAddress((void**)&Mbuf,g_M);
    cudaGetSymbolAddress((void**)&gM0p,g_gM0);
    cudaGetSymbolAddress((void**)&gM1p,g_gM1);
    cudaGetSymbolAddress((void**)&gB,  g_gB);
    float* M0  = Mbuf;
    float* M1  = Mbuf + NN*CC;     // aliased: gh1 lives here after M1 is consumed
    float* gh1 = M1;

    const int EB  = (EE + EPB-1)/EPB;

    prep_k<<<TBB + HBB + MBB + FBB + GBB, 256>>>(Wr, br, emb, z, F, coord, ei, ej);
    scanA_k<<<2*NBK, SCH>>>();
    scanC_k<<<2*NBK, SCH>>>();
    geomB_k<<<(EE+255)/256, 256>>>(coord, ei, ej);

    // ---- layer 0 forward
    edge_fwd0_k<<<EB, 256>>>(h0a);
    mmfwdC_k<<<G3B + G1B, 256>>>(M0, M1, h0a, Wmsg0, Wself0, Wmsg1, b0, h0b, s0, h1b);
    cudaMemsetAsync(Mbuf, 0, NN*CC*4*sizeof(float));   // zeros M0 AND gh1 (aliased M1)

    // ---- layer 1 forward (edge) + fused node fwd/readout/backward
    edge_fwd1_k<<<EB, 256>>>(h0b, h1b);
    l1_fused_k<<<T1B, 256>>>(M0, h0b, Wmsg0 + 4096, Wself0 + 4096, b0 + 64,
                             Wro1, bro1, Wro2, gM0p, gB, NN);

    // ---- layer 1 backward (j-sorted scatter)
    edge_bwd1_k<<<EB, 256>>>(h0b, h1b, gM0p, gB, gh1, F);

    // ---- layer 0 backward (combined GEMMs + i-sorted edge)
    bwd0mm_k<<<T1B + T3B, 256>>>(gB, s0, Wmsg0, gM0p, gh1, Wmsg1, gM1p);
    edge_bwd0_k<<<EB, 256>>>(h0a, gM0p, gM1p, F);
}